// round 9
// baseline (speedup 1.0000x reference)
#include <cuda_runtime.h>
#include <math.h>
#include <stdint.h>

// Problem constants
#define BB      2
#define DD      16
#define HHH     32
#define WWW     32
#define CC      256
#define N_TOK   16384
#define BN_TOK  32768
#define HID     1024
#define SPLITS  16
#define CHUNK   (N_TOK / SPLITS)
#define MX_SIZE ((size_t)BN_TOK * CC)
#define CTX_ELE ((size_t)CC * CC)

// GEMM smem: BK=32, row stride 36 floats; A/B 18432 B each; 3 stages
#define AB_BYTES    18432
#define STAGE_BYTES 36864
#define GEMM_SMEM   (3 * STAGE_BYTES)   // 110592 B/CTA; 2 CTAs = 216 KB < 228 KB

// ---------------- scratch ----------------
__device__ float g_n1  [(size_t)BN_TOK * CC];
__device__ float g_keys[(size_t)CC * BN_TOK];
__device__ float g_vals[(size_t)CC * BN_TOK];
__device__ float g_q   [(size_t)BN_TOK * CC];
__device__ float g_tx  [(size_t)BN_TOK * CC];
__device__ float g_h1  [(size_t)BN_TOK * HID];
__device__ float g_act [(size_t)BN_TOK * HID];
__device__ float g_ctxp[(size_t)BB * SPLITS * CC * CC];
__device__ float g_ctxT[(size_t)BB * CC * CC];
__device__ float g_ctxR[(size_t)BB * CC * CC];
__device__ float g_M   [(size_t)BB * CC * CC];
__device__ float g_wT  [27 * HID];
__device__ float g_rW  [4 * 65536 + 2 * 262144];   // tf32-rounded weights

__device__ __forceinline__ float cvt_tf32(float x) {
    uint32_t u;
    asm("cvt.rna.tf32.f32 %0, %1;" : "=r"(u) : "f"(x));
    return __uint_as_float(u);
}

#define CP16(dst, src) \
    asm volatile("cp.async.ca.shared.global [%0], [%1], 16;" :: "r"(dst), "l"(src))

// ---------------- TF32 tensor-core GEMM: 3-stage cp.async, BK=32, ldmatrix ----------------
// C = A[M,K] * B[N,K]^T (+bias_row +bias_col +resid). Inputs pre-rounded to TF32.
// 128x128 block tile, BK=32, 256 threads, 8 warps of 64x32 (m16n8k8 mma).
// Requires K % 32 == 0, K/32 >= 3. __launch_bounds__(256,2) keeps 2 CTAs/SM.
__global__ void __launch_bounds__(256, 2)
gemm_tf32(const float* __restrict__ A, const float* __restrict__ B, float* __restrict__ C,
          const float* __restrict__ bias_row, const float* __restrict__ bias_col,
          const float* __restrict__ resid,
          int M, int N, int K, int lda, int ldb, int ldc,
          long long sAo, long long sAi, long long sBo, long long sBi,
          long long sCo, long long sCi, int S, int round_out)
{
    extern __shared__ float smem_dyn[];
    uint32_t base = (uint32_t)__cvta_generic_to_shared(smem_dyn);

    int z  = blockIdx.z;
    int zo = z / S, zi = z - zo * S;
    const float* Ab = A + zo * sAo + zi * sAi;
    const float* Bb = B + zo * sBo + zi * sBi;
    float*       Cb = C + zo * sCo + zi * sCi;
    const float* Rb = resid ? (resid + zo * sCo + zi * sCi) : nullptr;

    int bm = blockIdx.y << 7, bn = blockIdx.x << 7;
    int tid = threadIdx.x;
    int r   = tid >> 3;          // 0..31
    int c4  = (tid & 7) << 2;    // 0,4,...,28

    const float* Ag = Ab + (size_t)(bm + r) * lda + c4;
    const float* Bg = Bb + (size_t)(bn + r) * ldb + c4;
    size_t ldA32 = (size_t)32 * lda, ldB32 = (size_t)32 * ldb;

    // store addresses within a stage (stage s: + s*STAGE_BYTES; B at +AB_BYTES)
    uint32_t stA = base + (uint32_t)(((r * 36) + c4) << 2);
    uint32_t stB = stA + (uint32_t)AB_BYTES;

    int lane = tid & 31, warp = tid >> 5;
    int wm = (warp >> 2) << 6;   // 0 or 64
    int wn = (warp & 3) << 5;    // 0,32,64,96
    int gq = lane >> 2, tg = lane & 3;

    // ldmatrix fragment addresses (stage 0); row stride 144 B -> conflict-free
    uint32_t a_off = base + (uint32_t)(((wm + (lane & 15)) * 36 + ((lane >> 4) << 2)) << 2);
    uint32_t b_off = base + (uint32_t)AB_BYTES
                   + (uint32_t)(((wn + ((lane >> 4) << 3) + (lane & 7)) * 36
                                + (((lane >> 3) & 1) << 2)) << 2);

    float acc[4][4][4];
#pragma unroll
    for (int i = 0; i < 4; i++)
#pragma unroll
        for (int j = 0; j < 4; j++)
#pragma unroll
            for (int l = 0; l < 4; l++) acc[i][j][l] = 0.f;

    int nt = K >> 5;

#define FILL_STAGE(sb)                                                         \
    do {                                                                       \
        CP16(stA + (sb),         Ag);                                          \
        CP16(stA + (sb) + 4608,  Ag + ldA32);                                  \
        CP16(stA + (sb) + 9216,  Ag + 2 * ldA32);                              \
        CP16(stA + (sb) + 13824, Ag + 3 * ldA32);                              \
        CP16(stB + (sb),         Bg);                                          \
        CP16(stB + (sb) + 4608,  Bg + ldB32);                                  \
        CP16(stB + (sb) + 9216,  Bg + 2 * ldB32);                              \
        CP16(stB + (sb) + 13824, Bg + 3 * ldB32);                              \
    } while (0)

    // prologue: issue tiles 0 and 1
    FILL_STAGE(0u);
    asm volatile("cp.async.commit_group;");
    Ag += 32; Bg += 32;
    FILL_STAGE((uint32_t)STAGE_BYTES);
    asm volatile("cp.async.commit_group;");
    asm volatile("cp.async.wait_group 1;" ::: "memory");
    __syncthreads();

    int stage = 0;                 // stage of tile being computed
    int wstage = 2;                // stage to write next prefetch into
    for (int i = 0; i < nt; i++) {
        if (i + 2 < nt) {
            Ag += 32; Bg += 32;
            uint32_t wb = (uint32_t)wstage * STAGE_BYTES;
            FILL_STAGE(wb);
            asm volatile("cp.async.commit_group;");
            wstage = (wstage == 2) ? 0 : wstage + 1;
        }

        uint32_t bufb = (uint32_t)stage * STAGE_BYTES;
#pragma unroll
        for (int kk = 0; kk < 4; kk++) {
            uint32_t kb = (uint32_t)(kk << 5);   // kk*8 floats = kk*32 bytes
            uint32_t a[4][4];
#pragma unroll
            for (int mt = 0; mt < 4; mt++) {
                uint32_t addr = a_off + bufb + kb + (uint32_t)(mt * 2304);
                asm volatile(
                    "ldmatrix.sync.aligned.m8n8.x4.shared.b16 {%0,%1,%2,%3}, [%4];"
                    : "=r"(a[mt][0]), "=r"(a[mt][1]), "=r"(a[mt][2]), "=r"(a[mt][3])
                    : "r"(addr));
            }
            uint32_t b[4][2];
            {
                uint32_t addr0 = b_off + bufb + kb;
                asm volatile(
                    "ldmatrix.sync.aligned.m8n8.x4.shared.b16 {%0,%1,%2,%3}, [%4];"
                    : "=r"(b[0][0]), "=r"(b[0][1]), "=r"(b[1][0]), "=r"(b[1][1])
                    : "r"(addr0));
                uint32_t addr1 = addr0 + 2304u;   // +16 rows
                asm volatile(
                    "ldmatrix.sync.aligned.m8n8.x4.shared.b16 {%0,%1,%2,%3}, [%4];"
                    : "=r"(b[2][0]), "=r"(b[2][1]), "=r"(b[3][0]), "=r"(b[3][1])
                    : "r"(addr1));
            }
#pragma unroll
            for (int mt = 0; mt < 4; mt++)
#pragma unroll
                for (int nt2 = 0; nt2 < 4; nt2++) {
                    asm volatile(
                        "mma.sync.aligned.m16n8k8.row.col.f32.tf32.tf32.f32 "
                        "{%0,%1,%2,%3}, {%4,%5,%6,%7}, {%8,%9}, {%0,%1,%2,%3};\n"
                        : "+f"(acc[mt][nt2][0]), "+f"(acc[mt][nt2][1]),
                          "+f"(acc[mt][nt2][2]), "+f"(acc[mt][nt2][3])
                        : "r"(a[mt][0]), "r"(a[mt][1]), "r"(a[mt][2]), "r"(a[mt][3]),
                          "r"(b[nt2][0]), "r"(b[nt2][1]));
                }
        }

        if (i + 1 < nt) {
            if (i + 2 < nt) { asm volatile("cp.async.wait_group 1;" ::: "memory"); }
            else            { asm volatile("cp.async.wait_group 0;" ::: "memory"); }
            __syncthreads();
        }
        stage = (stage == 2) ? 0 : stage + 1;
    }

    // epilogue
#pragma unroll
    for (int mt = 0; mt < 4; mt++) {
        int row0 = bm + wm + (mt << 4) + gq;
#pragma unroll
        for (int nt2 = 0; nt2 < 4; nt2++) {
            int col = bn + wn + (nt2 << 3) + (tg << 1);
            float bcx = 0.f, bcy = 0.f;
            if (bias_col) { float2 t = *(const float2*)&bias_col[col]; bcx = t.x; bcy = t.y; }
            float br0 = bias_row ? bias_row[row0] : 0.f;
            float br1 = bias_row ? bias_row[row0 + 8] : 0.f;
            size_t o0 = (size_t)row0 * ldc + col;
            size_t o1 = (size_t)(row0 + 8) * ldc + col;
            float2 v0, v1;
            v0.x = acc[mt][nt2][0] + br0 + bcx;
            v0.y = acc[mt][nt2][1] + br0 + bcy;
            v1.x = acc[mt][nt2][2] + br1 + bcx;
            v1.y = acc[mt][nt2][3] + br1 + bcy;
            if (Rb) {
                float2 r0v = *(const float2*)(Rb + o0);
                float2 r1v = *(const float2*)(Rb + o1);
                v0.x += r0v.x; v0.y += r0v.y;
                v1.x += r1v.x; v1.y += r1v.y;
            }
            if (round_out) {
                v0.x = cvt_tf32(v0.x); v0.y = cvt_tf32(v0.y);
                v1.x = cvt_tf32(v1.x); v1.y = cvt_tf32(v1.y);
            }
            *(float2*)(Cb + o0) = v0;
            *(float2*)(Cb + o1) = v1;
        }
    }
}

// ---------------- fused prep: round 6 weight tensors + transpose dw weights -------------
__global__ void prep_kernel(const float* __restrict__ Wk, const float* __restrict__ Wq,
                            const float* __restrict__ Wv, const float* __restrict__ Wr,
                            const float* __restrict__ fc1, const float* __restrict__ fc2,
                            const float* __restrict__ dw,
                            float* __restrict__ rW, float* __restrict__ wT)
{
    int i = blockIdx.x * 256 + threadIdx.x;
    if (i < 65536)        rW[i] = cvt_tf32(Wk[i]);
    else if (i < 131072)  rW[i] = cvt_tf32(Wq[i - 65536]);
    else if (i < 196608)  rW[i] = cvt_tf32(Wv[i - 131072]);
    else if (i < 262144)  rW[i] = cvt_tf32(Wr[i - 196608]);
    else if (i < 524288)  rW[i] = cvt_tf32(fc1[i - 262144]);
    else if (i < 786432)  rW[i] = cvt_tf32(fc2[i - 524288]);
    else {
        int j = i - 786432;
        if (j < 27 * HID) {
            int hc = j / 27;
            int t = j - hc * 27;
            wT[t * HID + hc] = dw[j];
        }
    }
}

// ---------------- LayerNorm over C=256 (outputs TF32-rounded) ----------------
__global__ void ln_kernel(const float* __restrict__ x, const float* __restrict__ g,
                          const float* __restrict__ b, float* __restrict__ out)
{
    int row  = (blockIdx.x << 3) + (threadIdx.x >> 5);
    int lane = threadIdx.x & 31;
    const float4* p = (const float4*)(x + (size_t)row * CC);
    float4 v0 = p[lane], v1 = p[lane + 32];
    float s = v0.x + v0.y + v0.z + v0.w + v1.x + v1.y + v1.z + v1.w;
    float q = v0.x*v0.x + v0.y*v0.y + v0.z*v0.z + v0.w*v0.w
            + v1.x*v1.x + v1.y*v1.y + v1.z*v1.z + v1.w*v1.w;
#pragma unroll
    for (int o = 16; o; o >>= 1) {
        s += __shfl_xor_sync(0xffffffffu, s, o);
        q += __shfl_xor_sync(0xffffffffu, q, o);
    }
    float mean = s * (1.f / 256.f);
    float var  = q * (1.f / 256.f) - mean * mean;
    float rs   = rsqrtf(var + 1e-5f);
    const float4 g0 = ((const float4*)g)[lane], g1 = ((const float4*)g)[lane + 32];
    const float4 b0 = ((const float4*)b)[lane], b1 = ((const float4*)b)[lane + 32];
    float4 o0, o1;
    o0.x = cvt_tf32((v0.x - mean) * rs * g0.x + b0.x);
    o0.y = cvt_tf32((v0.y - mean) * rs * g0.y + b0.y);
    o0.z = cvt_tf32((v0.z - mean) * rs * g0.z + b0.z);
    o0.w = cvt_tf32((v0.w - mean) * rs * g0.w + b0.w);
    o1.x = cvt_tf32((v1.x - mean) * rs * g1.x + b1.x);
    o1.y = cvt_tf32((v1.y - mean) * rs * g1.y + b1.y);
    o1.z = cvt_tf32((v1.z - mean) * rs * g1.z + b1.z);
    o1.w = cvt_tf32((v1.w - mean) * rs * g1.w + b1.w);
    float4* po = (float4*)(out + (size_t)row * CC);
    po[lane] = o0; po[lane + 32] = o1;
}

// ---------------- softmax over spatial dim (output TF32-rounded) ----------------
__global__ void softmax_spatial_kernel(float* __restrict__ keys)
{
    __shared__ float red[256];
    int k = blockIdx.x >> 1, b = blockIdx.x & 1;
    float* row = keys + (size_t)k * BN_TOK + (size_t)b * N_TOK;
    int t = threadIdx.x;

    float m = -1e30f;
    for (int i = t; i < N_TOK; i += 256) m = fmaxf(m, row[i]);
    red[t] = m; __syncthreads();
    for (int s = 128; s > 0; s >>= 1) { if (t < s) red[t] = fmaxf(red[t], red[t + s]); __syncthreads(); }
    m = red[0]; __syncthreads();

    float sum = 0.f;
    for (int i = t; i < N_TOK; i += 256) { float e = __expf(row[i] - m); row[i] = e; sum += e; }
    red[t] = sum; __syncthreads();
    for (int s = 128; s > 0; s >>= 1) { if (t < s) red[t] += red[t + s]; __syncthreads(); }
    float inv = 1.f / red[0];
    for (int i = t; i < N_TOK; i += 256) row[i] = cvt_tf32(row[i] * inv);
}

// ---------------- softmax over channel dim (output TF32-rounded) ----------------
__global__ void softmax_channel_kernel(float* __restrict__ q)
{
    int row  = (blockIdx.x << 3) + (threadIdx.x >> 5);
    int lane = threadIdx.x & 31;
    float4* p = (float4*)(q + (size_t)row * CC);
    float4 v0 = p[lane], v1 = p[lane + 32];
    float m = fmaxf(fmaxf(fmaxf(v0.x, v0.y), fmaxf(v0.z, v0.w)),
                    fmaxf(fmaxf(v1.x, v1.y), fmaxf(v1.z, v1.w)));
#pragma unroll
    for (int o = 16; o; o >>= 1) m = fmaxf(m, __shfl_xor_sync(0xffffffffu, m, o));
    v0.x = __expf(v0.x - m); v0.y = __expf(v0.y - m);
    v0.z = __expf(v0.z - m); v0.w = __expf(v0.w - m);
    v1.x = __expf(v1.x - m); v1.y = __expf(v1.y - m);
    v1.z = __expf(v1.z - m); v1.w = __expf(v1.w - m);
    float s = v0.x + v0.y + v0.z + v0.w + v1.x + v1.y + v1.z + v1.w;
#pragma unroll
    for (int o = 16; o; o >>= 1) s += __shfl_xor_sync(0xffffffffu, s, o);
    float inv = 1.f / s;
    v0.x = cvt_tf32(v0.x * inv); v0.y = cvt_tf32(v0.y * inv);
    v0.z = cvt_tf32(v0.z * inv); v0.w = cvt_tf32(v0.w * inv);
    v1.x = cvt_tf32(v1.x * inv); v1.y = cvt_tf32(v1.y * inv);
    v1.z = cvt_tf32(v1.z * inv); v1.w = cvt_tf32(v1.w * inv);
    p[lane] = v0; p[lane + 32] = v1;
}

// ------- split-K reduce -> ctx (d_out, fp32) + ctx^T (rounded) + ctx rounded ------------
__global__ void ctx_reduce_kernel(const float* __restrict__ part, float* __restrict__ ctx,
                                  float* __restrict__ ctxT, float* __restrict__ ctxR)
{
    int i = blockIdx.x * 256 + threadIdx.x;
    int b = i >> 16;
    int r = i & 65535;
    float s = 0.f;
#pragma unroll
    for (int sp = 0; sp < SPLITS; sp++)
        s += part[((size_t)(b * SPLITS + sp)) * CTX_ELE + r];
    ctx[i] = s;
    float sr = cvt_tf32(s);
    ctxR[i] = sr;
    int k = r >> 8, v = r & 255;
    ctxT[((size_t)b << 16) + (v << 8) + k] = sr;
}

// ---------------- depthwise 3x3x3 conv + exact GELU (output TF32-rounded) ---------------
__global__ void __launch_bounds__(256)
dwconv_gelu_kernel(const float* __restrict__ h1, const float* __restrict__ wT,
                   const float* __restrict__ wb, float* __restrict__ out)
{
    int t = blockIdx.x * 256 + threadIdx.x;
    int hc4 = (t & 255) << 2;
    int bn  = t >> 8;
    int n = bn & (N_TOK - 1);
    int b = bn >> 14;
    int d = n >> 10;
    int h = (n >> 5) & 31;
    int w = n & 31;

    float4 s = *(const float4*)&wb[hc4];
    const float* base = h1 + ((size_t)b * N_TOK) * HID + hc4;

#pragma unroll
    for (int kd = -1; kd <= 1; kd++) {
        int zd = d + kd; if ((unsigned)zd >= DD) continue;
#pragma unroll
        for (int kh = -1; kh <= 1; kh++) {
            int zh = h + kh; if ((unsigned)zh >= HHH) continue;
#pragma unroll
            for (int kw = -1; kw <= 1; kw++) {
                int zw = w + kw; if ((unsigned)zw >= WWW) continue;
                int nn = (zd * HHH + zh) * WWW + zw;
                int tap = (kd + 1) * 9 + (kh + 1) * 3 + (kw + 1);
                float4 v = *(const float4*)(base + (size_t)nn * HID);
                float4 wv = *(const float4*)&wT[tap * HID + hc4];
                s.x = fmaf(v.x, wv.x, s.x);
                s.y = fmaf(v.y, wv.y, s.y);
                s.z = fmaf(v.z, wv.z, s.z);
                s.w = fmaf(v.w, wv.w, s.w);
            }
        }
    }
    const float k = 0.70710678118654752f;
    float4 o;
    o.x = cvt_tf32(0.5f * s.x * (1.0f + erff(s.x * k)));
    o.y = cvt_tf32(0.5f * s.y * (1.0f + erff(s.y * k)));
    o.z = cvt_tf32(0.5f * s.z * (1.0f + erff(s.z * k)));
    o.w = cvt_tf32(0.5f * s.w * (1.0f + erff(s.w * k)));
    *(float4*)&out[((size_t)bn * HID) + hc4] = o;
}

// ---------------- launch ----------------
extern "C" void kernel_launch(void* const* d_in, const int* in_sizes, int n_in,
                              void* d_out, int out_size)
{
    const float* x     = (const float*)d_in[0];
    const float* ln1_g = (const float*)d_in[1];
    const float* ln1_b = (const float*)d_in[2];
    const float* Wk    = (const float*)d_in[3];
    const float* bk    = (const float*)d_in[4];
    const float* Wq    = (const float*)d_in[5];
    const float* bq    = (const float*)d_in[6];
    const float* Wv    = (const float*)d_in[7];
    const float* bv    = (const float*)d_in[8];
    const float* Wr    = (const float*)d_in[9];
    const float* br    = (const float*)d_in[10];
    const float* ln2_g = (const float*)d_in[11];
    const float* ln2_b = (const float*)d_in[12];
    const float* fc1_W = (const float*)d_in[13];
    const float* fc1_b = (const float*)d_in[14];
    const float* dw_W  = (const float*)d_in[15];
    const float* dw_b  = (const float*)d_in[16];
    const float* fc2_W = (const float*)d_in[17];
    const float* fc2_b = (const float*)d_in[18];

    float *n1, *keys, *vals, *q, *tx, *h1, *act, *ctxp, *ctxT, *ctxR, *Mbuf, *wT, *rW;
    cudaGetSymbolAddress((void**)&n1,   g_n1);
    cudaGetSymbolAddress((void**)&keys, g_keys);
    cudaGetSymbolAddress((void**)&vals, g_vals);
    cudaGetSymbolAddress((void**)&q,    g_q);
    cudaGetSymbolAddress((void**)&tx,   g_tx);
    cudaGetSymbolAddress((void**)&h1,   g_h1);
    cudaGetSymbolAddress((void**)&act,  g_act);
    cudaGetSymbolAddress((void**)&ctxp, g_ctxp);
    cudaGetSymbolAddress((void**)&ctxT, g_ctxT);
    cudaGetSymbolAddress((void**)&ctxR, g_ctxR);
    cudaGetSymbolAddress((void**)&Mbuf, g_M);
    cudaGetSymbolAddress((void**)&wT,   g_wT);
    cudaGetSymbolAddress((void**)&rW,   g_rW);

    cudaFuncSetAttribute(gemm_tf32, cudaFuncAttributeMaxDynamicSharedMemorySize, GEMM_SMEM);

    float* rWk  = rW;
    float* rWq  = rW + 65536;
    float* rWv  = rW + 131072;
    float* rWr  = rW + 196608;
    float* rfc1 = rW + 262144;
    float* rfc2 = rW + 524288;

    float* mx  = (float*)d_out;
    float* ctx = mx + MX_SIZE;

    // 0. fused prep (weight rounding + dw transpose)
    prep_kernel<<<(786432 + 27648 + 255) / 256, 256>>>(Wk, Wq, Wv, Wr, fc1_W, fc2_W,
                                                       dw_W, rW, wT);

    // 1. LN1 (TF32-rounded output)
    ln_kernel<<<BN_TOK / 8, 256>>>(x, ln1_g, ln1_b, n1);

    // 2. keys = rWk @ n1^T + bk -> [C, BN]
    gemm_tf32<<<dim3(BN_TOK/128, CC/128, 1), 256, GEMM_SMEM>>>(rWk, n1, keys, bk, nullptr, nullptr,
        CC, BN_TOK, CC, CC, CC, BN_TOK, 0, 0, 0, 0, 0, 0, 1, 0);

    // 3. vals = rWv @ n1^T + bv -> [C, BN] (rounded: feeds context GEMM)
    gemm_tf32<<<dim3(BN_TOK/128, CC/128, 1), 256, GEMM_SMEM>>>(rWv, n1, vals, bv, nullptr, nullptr,
        CC, BN_TOK, CC, CC, CC, BN_TOK, 0, 0, 0, 0, 0, 0, 1, 1);

    // 4. q = n1 @ rWq^T + bq -> [BN, C]
    gemm_tf32<<<dim3(CC/128, BN_TOK/128, 1), 256, GEMM_SMEM>>>(n1, rWq, q, nullptr, bq, nullptr,
        BN_TOK, CC, CC, CC, CC, CC, 0, 0, 0, 0, 0, 0, 1, 0);

    // 5. spatial softmax (rounded)
    softmax_spatial_kernel<<<2 * CC, 256>>>(keys);

    // 6. channel softmax (rounded)
    softmax_channel_kernel<<<BN_TOK / 8, 256>>>(q);

    // 7. context partials (split-K over spatial)
    gemm_tf32<<<dim3(2, 2, BB * SPLITS), 256, GEMM_SMEM>>>(keys, vals, ctxp,
        nullptr, nullptr, nullptr,
        CC, CC, CHUNK, BN_TOK, BN_TOK, CC,
        (long long)N_TOK, (long long)CHUNK,
        (long long)N_TOK, (long long)CHUNK,
        (long long)SPLITS * CTX_ELE, (long long)CTX_ELE, SPLITS, 0);

    // 8. reduce partials -> ctx (fp32, d_out) + ctxT + ctxR (rounded)
    ctx_reduce_kernel<<<512, 256>>>(ctxp, ctx, ctxT, ctxR);

    // 9a. M = rWr @ ctxR^T per batch: M[c,k] = sum_v Wr[c,v] ctx[k,v]  (tiny, rounded)
    gemm_tf32<<<dim3(2, 2, BB), 256, GEMM_SMEM>>>(rWr, ctxR, Mbuf,
        nullptr, nullptr, nullptr,
        CC, CC, CC, CC, CC, CC,
        0, 0, (long long)CTX_ELE, 0, (long long)CTX_ELE, 0, 1, 1);

    // 9b. tx = x + q_sm @ M^T + br   (fused attended+reprojection)
    gemm_tf32<<<dim3(CC/128, N_TOK/128, BB), 256, GEMM_SMEM>>>(q, Mbuf, tx,
        nullptr, br, x,
        N_TOK, CC, CC, CC, CC, CC,
        (long long)N_TOK * CC, 0, (long long)CTX_ELE, 0, (long long)N_TOK * CC, 0, 1, 0);

    // 11. LN2 (TF32-rounded output)
    ln_kernel<<<BN_TOK / 8, 256>>>(tx, ln2_g, ln2_b, n1);

    // 12. h1 = n2 @ rfc1^T + fc1_b (fp32: feeds conv)
    gemm_tf32<<<dim3(HID/128, BN_TOK/128, 1), 256, GEMM_SMEM>>>(n1, rfc1, h1, nullptr, fc1_b, nullptr,
        BN_TOK, HID, CC, CC, CC, HID, 0, 0, 0, 0, 0, 0, 1, 0);

    // 13. depthwise conv + GELU (rounded output: feeds fc2 GEMM)
    dwconv_gelu_kernel<<<(BN_TOK * HID / 4) / 256, 256>>>(h1, wT, dw_b, act);

    // 14. mx = tx + act @ rfc2^T + fc2_b (fp32, direct to d_out)
    gemm_tf32<<<dim3(CC/128, BN_TOK/128, 1), 256, GEMM_SMEM>>>(act, rfc2, mx, nullptr, fc2_b, tx,
        BN_TOK, CC, HID, HID, HID, CC, 0, 0, 0, 0, 0, 0, 1, 0);
}

// round 10
// speedup vs baseline: 1.4530x; 1.4530x over previous
#include <cuda_runtime.h>
#include <cuda_fp16.h>
#include <math.h>
#include <stdint.h>

// Problem constants
#define BB      2
#define DD      16
#define HHH     32
#define WWW     32
#define CC      256
#define N_TOK   16384
#define BN_TOK  32768
#define HID     1024
#define SPLITS  16
#define CHUNK   (N_TOK / SPLITS)
#define MX_SIZE ((size_t)BN_TOK * CC)
#define CTX_ELE ((size_t)CC * CC)

// GEMM smem (fp16): BK=32 halfs, row stride 40 halfs = 80B; A/B tiles 128*80 = 10240B
#define AB_BYTES    10240
#define STAGE_BYTES 20480
#define GEMM_SMEM   (3 * STAGE_BYTES)   // 61440 B/CTA; 2 CTAs = 120 KB < 228 KB

// ---------------- scratch ----------------
__device__ __half g_n1h  [(size_t)BN_TOK * CC];
__device__ float  g_keysf[(size_t)CC * BN_TOK];
__device__ __half g_keysh[(size_t)CC * BN_TOK];
__device__ __half g_valsh[(size_t)CC * BN_TOK];
__device__ float  g_qf   [(size_t)BN_TOK * CC];
__device__ __half g_qh   [(size_t)BN_TOK * CC];
__device__ float  g_tx   [(size_t)BN_TOK * CC];
__device__ __half g_h1h  [(size_t)BN_TOK * HID];
__device__ __half g_acth [(size_t)BN_TOK * HID];
__device__ float  g_ctxp [(size_t)BB * SPLITS * CC * CC];
__device__ __half g_ctxRh[(size_t)BB * CC * CC];
__device__ __half g_Mh   [(size_t)BB * CC * CC];
__device__ float  g_wT   [27 * HID];
__device__ __half g_rWh  [4 * 65536 + 2 * 262144];   // fp16 weights

#define CP16(dst, src) \
    asm volatile("cp.async.ca.shared.global [%0], [%1], 16;" :: "r"(dst), "l"(src))

// ---------------- FP16 tensor-core GEMM: 3-stage cp.async + ldmatrix, m16n8k16 ----------
// C(f32) and/or Ch(f16) = A[M,K]h * B[N,K]h^T (+bias_row +bias_col +resid), f32 accum.
// 128x128 block tile, BK=32 halfs, 256 threads, 8 warps of 64x32.
// K % 32 == 0, K/32 >= 3. __launch_bounds__(256,2) keeps 2 CTAs/SM.
__global__ void __launch_bounds__(256, 2)
gemm_f16(const __half* __restrict__ A, const __half* __restrict__ B,
         float* __restrict__ C, __half* __restrict__ Ch,
         const float* __restrict__ bias_row, const float* __restrict__ bias_col,
         const float* __restrict__ resid,
         int M, int N, int K, int lda, int ldb, int ldc,
         long long sAo, long long sAi, long long sBo, long long sBi,
         long long sCo, long long sCi, int S)
{
    extern __shared__ __half smem_dyn[];
    uint32_t base = (uint32_t)__cvta_generic_to_shared(smem_dyn);

    int z  = blockIdx.z;
    int zo = z / S, zi = z - zo * S;
    const __half* Ab = A + zo * sAo + zi * sAi;
    const __half* Bb = B + zo * sBo + zi * sBi;
    float*  Cb  = C  ? (C  + zo * sCo + zi * sCi) : nullptr;
    __half* Chb = Ch ? (Ch + zo * sCo + zi * sCi) : nullptr;
    const float* Rb = resid ? (resid + zo * sCo + zi * sCi) : nullptr;

    int bm = blockIdx.y << 7, bn = blockIdx.x << 7;
    int tid = threadIdx.x;
    int r   = tid >> 2;          // 0..63
    int c8  = (tid & 3) << 3;    // 0,8,16,24 halfs (16B units)

    const __half* Ag = Ab + (size_t)(bm + r) * lda + c8;
    const __half* Bg = Bb + (size_t)(bn + r) * ldb + c8;
    size_t ldA64 = (size_t)64 * lda, ldB64 = (size_t)64 * ldb;

    // store addresses (row stride 80B); stage s at +s*STAGE_BYTES, B at +AB_BYTES
    uint32_t stA0 = base + (uint32_t)(r * 80 + (c8 << 1));
    uint32_t stA1 = stA0 + (uint32_t)(64 * 80);
    uint32_t stB0 = stA0 + (uint32_t)AB_BYTES;
    uint32_t stB1 = stA1 + (uint32_t)AB_BYTES;

    int lane = tid & 31, warp = tid >> 5;
    int wm = (warp >> 2) << 6;   // 0 or 64
    int wn = (warp & 3) << 5;    // 0,32,64,96
    int gq = lane >> 2, tg = lane & 3;

    // ldmatrix fragment addresses (stage 0)
    uint32_t a_off = base + (uint32_t)((wm + (lane & 15)) * 80 + ((lane >> 4) << 4));
    uint32_t b_off = base + (uint32_t)AB_BYTES
                   + (uint32_t)((wn + ((lane >> 4) << 3) + (lane & 7)) * 80
                                + (((lane >> 3) & 1) << 4));

    float acc[4][4][4];
#pragma unroll
    for (int i = 0; i < 4; i++)
#pragma unroll
        for (int j = 0; j < 4; j++)
#pragma unroll
            for (int l = 0; l < 4; l++) acc[i][j][l] = 0.f;

    int nt = K >> 5;

#define FILL_STAGE(sb)                             \
    do {                                           \
        CP16(stA0 + (sb), Ag);                     \
        CP16(stA1 + (sb), Ag + ldA64);             \
        CP16(stB0 + (sb), Bg);                     \
        CP16(stB1 + (sb), Bg + ldB64);             \
    } while (0)

    // prologue: issue tiles 0 and 1
    FILL_STAGE(0u);
    asm volatile("cp.async.commit_group;");
    Ag += 32; Bg += 32;
    FILL_STAGE((uint32_t)STAGE_BYTES);
    asm volatile("cp.async.commit_group;");
    asm volatile("cp.async.wait_group 1;" ::: "memory");
    __syncthreads();

    int stage = 0, wstage = 2;
    for (int i = 0; i < nt; i++) {
        if (i + 2 < nt) {
            Ag += 32; Bg += 32;
            uint32_t wb = (uint32_t)wstage * STAGE_BYTES;
            FILL_STAGE(wb);
            asm volatile("cp.async.commit_group;");
            wstage = (wstage == 2) ? 0 : wstage + 1;
        }

        uint32_t bufb = (uint32_t)stage * STAGE_BYTES;
#pragma unroll
        for (int kk = 0; kk < 2; kk++) {           // two k16 steps per BK=32
            uint32_t kb = (uint32_t)(kk << 5);     // 16 halfs = 32 bytes
            uint32_t a[4][4];
#pragma unroll
            for (int mt = 0; mt < 4; mt++) {
                uint32_t addr = a_off + bufb + kb + (uint32_t)(mt * 1280);
                asm volatile(
                    "ldmatrix.sync.aligned.m8n8.x4.shared.b16 {%0,%1,%2,%3}, [%4];"
                    : "=r"(a[mt][0]), "=r"(a[mt][1]), "=r"(a[mt][2]), "=r"(a[mt][3])
                    : "r"(addr));
            }
            uint32_t b[4][2];
            {
                uint32_t addr0 = b_off + bufb + kb;
                asm volatile(
                    "ldmatrix.sync.aligned.m8n8.x4.shared.b16 {%0,%1,%2,%3}, [%4];"
                    : "=r"(b[0][0]), "=r"(b[0][1]), "=r"(b[1][0]), "=r"(b[1][1])
                    : "r"(addr0));
                uint32_t addr1 = addr0 + 1280u;    // +16 N-rows
                asm volatile(
                    "ldmatrix.sync.aligned.m8n8.x4.shared.b16 {%0,%1,%2,%3}, [%4];"
                    : "=r"(b[2][0]), "=r"(b[2][1]), "=r"(b[3][0]), "=r"(b[3][1])
                    : "r"(addr1));
            }
#pragma unroll
            for (int mt = 0; mt < 4; mt++)
#pragma unroll
                for (int nt2 = 0; nt2 < 4; nt2++) {
                    asm volatile(
                        "mma.sync.aligned.m16n8k16.row.col.f32.f16.f16.f32 "
                        "{%0,%1,%2,%3}, {%4,%5,%6,%7}, {%8,%9}, {%0,%1,%2,%3};\n"
                        : "+f"(acc[mt][nt2][0]), "+f"(acc[mt][nt2][1]),
                          "+f"(acc[mt][nt2][2]), "+f"(acc[mt][nt2][3])
                        : "r"(a[mt][0]), "r"(a[mt][1]), "r"(a[mt][2]), "r"(a[mt][3]),
                          "r"(b[nt2][0]), "r"(b[nt2][1]));
                }
        }

        if (i + 1 < nt) {
            if (i + 2 < nt) { asm volatile("cp.async.wait_group 1;" ::: "memory"); }
            else            { asm volatile("cp.async.wait_group 0;" ::: "memory"); }
            __syncthreads();
        }
        stage = (stage == 2) ? 0 : stage + 1;
    }

    // epilogue
#pragma unroll
    for (int mt = 0; mt < 4; mt++) {
        int row0 = bm + wm + (mt << 4) + gq;
#pragma unroll
        for (int nt2 = 0; nt2 < 4; nt2++) {
            int col = bn + wn + (nt2 << 3) + (tg << 1);
            float bcx = 0.f, bcy = 0.f;
            if (bias_col) { float2 t = *(const float2*)&bias_col[col]; bcx = t.x; bcy = t.y; }
            float br0 = bias_row ? bias_row[row0] : 0.f;
            float br1 = bias_row ? bias_row[row0 + 8] : 0.f;
            size_t o0 = (size_t)row0 * ldc + col;
            size_t o1 = (size_t)(row0 + 8) * ldc + col;
            float2 v0, v1;
            v0.x = acc[mt][nt2][0] + br0 + bcx;
            v0.y = acc[mt][nt2][1] + br0 + bcy;
            v1.x = acc[mt][nt2][2] + br1 + bcx;
            v1.y = acc[mt][nt2][3] + br1 + bcy;
            if (Rb) {
                float2 r0v = *(const float2*)(Rb + o0);
                float2 r1v = *(const float2*)(Rb + o1);
                v0.x += r0v.x; v0.y += r0v.y;
                v1.x += r1v.x; v1.y += r1v.y;
            }
            if (Cb) {
                *(float2*)(Cb + o0) = v0;
                *(float2*)(Cb + o1) = v1;
            }
            if (Chb) {
                *(__half2*)(Chb + o0) = __floats2half2_rn(v0.x, v0.y);
                *(__half2*)(Chb + o1) = __floats2half2_rn(v1.x, v1.y);
            }
        }
    }
}

// ---------------- fused prep: weights -> fp16 + transpose dw weights ----------------
__global__ void prep_kernel(const float* __restrict__ Wk, const float* __restrict__ Wq,
                            const float* __restrict__ Wv, const float* __restrict__ Wr,
                            const float* __restrict__ fc1, const float* __restrict__ fc2,
                            const float* __restrict__ dw,
                            __half* __restrict__ rW, float* __restrict__ wT)
{
    int i = blockIdx.x * 256 + threadIdx.x;
    if (i < 65536)        rW[i] = __float2half_rn(Wk[i]);
    else if (i < 131072)  rW[i] = __float2half_rn(Wq[i - 65536]);
    else if (i < 196608)  rW[i] = __float2half_rn(Wv[i - 131072]);
    else if (i < 262144)  rW[i] = __float2half_rn(Wr[i - 196608]);
    else if (i < 524288)  rW[i] = __float2half_rn(fc1[i - 262144]);
    else if (i < 786432)  rW[i] = __float2half_rn(fc2[i - 524288]);
    else {
        int j = i - 786432;
        if (j < 27 * HID) {
            int hc = j / 27;
            int t = j - hc * 27;
            wT[t * HID + hc] = dw[j];
        }
    }
}

// ---------------- LayerNorm over C=256 (fp32 in -> fp16 out) ----------------
__global__ void ln_kernel(const float* __restrict__ x, const float* __restrict__ g,
                          const float* __restrict__ b, __half* __restrict__ out)
{
    int row  = (blockIdx.x << 3) + (threadIdx.x >> 5);
    int lane = threadIdx.x & 31;
    const float4* p = (const float4*)(x + (size_t)row * CC);
    float4 v0 = p[lane], v1 = p[lane + 32];
    float s = v0.x + v0.y + v0.z + v0.w + v1.x + v1.y + v1.z + v1.w;
    float q = v0.x*v0.x + v0.y*v0.y + v0.z*v0.z + v0.w*v0.w
            + v1.x*v1.x + v1.y*v1.y + v1.z*v1.z + v1.w*v1.w;
#pragma unroll
    for (int o = 16; o; o >>= 1) {
        s += __shfl_xor_sync(0xffffffffu, s, o);
        q += __shfl_xor_sync(0xffffffffu, q, o);
    }
    float mean = s * (1.f / 256.f);
    float var  = q * (1.f / 256.f) - mean * mean;
    float rs   = rsqrtf(var + 1e-5f);
    const float4 g0 = ((const float4*)g)[lane], g1 = ((const float4*)g)[lane + 32];
    const float4 b0 = ((const float4*)b)[lane], b1 = ((const float4*)b)[lane + 32];
    __half2* po = (__half2*)(out + (size_t)row * CC);
    po[2*lane]      = __floats2half2_rn((v0.x-mean)*rs*g0.x+b0.x, (v0.y-mean)*rs*g0.y+b0.y);
    po[2*lane+1]    = __floats2half2_rn((v0.z-mean)*rs*g0.z+b0.z, (v0.w-mean)*rs*g0.w+b0.w);
    po[2*lane+64]   = __floats2half2_rn((v1.x-mean)*rs*g1.x+b1.x, (v1.y-mean)*rs*g1.y+b1.y);
    po[2*lane+65]   = __floats2half2_rn((v1.z-mean)*rs*g1.z+b1.z, (v1.w-mean)*rs*g1.w+b1.w);
}

// ---------------- softmax over spatial dim (fp32 in -> fp16 out) ----------------
__global__ void softmax_spatial_kernel(const float* __restrict__ keysf,
                                       __half* __restrict__ keysh)
{
    __shared__ float red[256];
    int k = blockIdx.x >> 1, b = blockIdx.x & 1;
    const float* row = keysf + (size_t)k * BN_TOK + (size_t)b * N_TOK;
    __half* rowo = keysh + (size_t)k * BN_TOK + (size_t)b * N_TOK;
    int t = threadIdx.x;

    float m = -1e30f;
    for (int i = t; i < N_TOK; i += 256) m = fmaxf(m, row[i]);
    red[t] = m; __syncthreads();
    for (int s = 128; s > 0; s >>= 1) { if (t < s) red[t] = fmaxf(red[t], red[t + s]); __syncthreads(); }
    m = red[0]; __syncthreads();

    float sum = 0.f;
    for (int i = t; i < N_TOK; i += 256) sum += __expf(row[i] - m);
    red[t] = sum; __syncthreads();
    for (int s = 128; s > 0; s >>= 1) { if (t < s) red[t] += red[t + s]; __syncthreads(); }
    float inv = 1.f / red[0];
    for (int i = t; i < N_TOK; i += 256)
        rowo[i] = __float2half_rn(__expf(row[i] - m) * inv);
}

// ---------------- softmax over channel dim (fp32 in -> fp16 out) ----------------
__global__ void softmax_channel_kernel(const float* __restrict__ qf, __half* __restrict__ qh)
{
    int row  = (blockIdx.x << 3) + (threadIdx.x >> 5);
    int lane = threadIdx.x & 31;
    const float4* p = (const float4*)(qf + (size_t)row * CC);
    float4 v0 = p[lane], v1 = p[lane + 32];
    float m = fmaxf(fmaxf(fmaxf(v0.x, v0.y), fmaxf(v0.z, v0.w)),
                    fmaxf(fmaxf(v1.x, v1.y), fmaxf(v1.z, v1.w)));
#pragma unroll
    for (int o = 16; o; o >>= 1) m = fmaxf(m, __shfl_xor_sync(0xffffffffu, m, o));
    v0.x = __expf(v0.x - m); v0.y = __expf(v0.y - m);
    v0.z = __expf(v0.z - m); v0.w = __expf(v0.w - m);
    v1.x = __expf(v1.x - m); v1.y = __expf(v1.y - m);
    v1.z = __expf(v1.z - m); v1.w = __expf(v1.w - m);
    float s = v0.x + v0.y + v0.z + v0.w + v1.x + v1.y + v1.z + v1.w;
#pragma unroll
    for (int o = 16; o; o >>= 1) s += __shfl_xor_sync(0xffffffffu, s, o);
    float inv = 1.f / s;
    __half2* po = (__half2*)(qh + (size_t)row * CC);
    po[2*lane]    = __floats2half2_rn(v0.x * inv, v0.y * inv);
    po[2*lane+1]  = __floats2half2_rn(v0.z * inv, v0.w * inv);
    po[2*lane+64] = __floats2half2_rn(v1.x * inv, v1.y * inv);
    po[2*lane+65] = __floats2half2_rn(v1.z * inv, v1.w * inv);
}

// -------- split-K reduce -> ctx (d_out, fp32) + ctx fp16 (for M GEMM) ----------
__global__ void ctx_reduce_kernel(const float* __restrict__ part, float* __restrict__ ctx,
                                  __half* __restrict__ ctxRh)
{
    int i = blockIdx.x * 256 + threadIdx.x;
    int b = i >> 16;
    int r = i & 65535;
    float s = 0.f;
#pragma unroll
    for (int sp = 0; sp < SPLITS; sp++)
        s += part[((size_t)(b * SPLITS + sp)) * CTX_ELE + r];
    ctx[i] = s;
    ctxRh[i] = __float2half_rn(s);
}

// ------- depthwise 3x3x3 conv + exact GELU (fp16 in, fp32 accum, fp16 out) -------
__global__ void __launch_bounds__(256)
dwconv_gelu_kernel(const __half* __restrict__ h1h, const float* __restrict__ wT,
                   const float* __restrict__ wb, __half* __restrict__ out)
{
    int t = blockIdx.x * 256 + threadIdx.x;
    int hc4 = (t & 255) << 2;
    int bn  = t >> 8;
    int n = bn & (N_TOK - 1);
    int b = bn >> 14;
    int d = n >> 10;
    int h = (n >> 5) & 31;
    int w = n & 31;

    float4 s = *(const float4*)&wb[hc4];
    const __half* base = h1h + ((size_t)b * N_TOK) * HID + hc4;

#pragma unroll
    for (int kd = -1; kd <= 1; kd++) {
        int zd = d + kd; if ((unsigned)zd >= DD) continue;
#pragma unroll
        for (int kh = -1; kh <= 1; kh++) {
            int zh = h + kh; if ((unsigned)zh >= HHH) continue;
#pragma unroll
            for (int kw = -1; kw <= 1; kw++) {
                int zw = w + kw; if ((unsigned)zw >= WWW) continue;
                int nn = (zd * HHH + zh) * WWW + zw;
                int tap = (kd + 1) * 9 + (kh + 1) * 3 + (kw + 1);
                const __half2* pp = (const __half2*)(base + (size_t)nn * HID);
                float2 f0 = __half22float2(pp[0]);
                float2 f1 = __half22float2(pp[1]);
                float4 wv = *(const float4*)&wT[tap * HID + hc4];
                s.x = fmaf(f0.x, wv.x, s.x);
                s.y = fmaf(f0.y, wv.y, s.y);
                s.z = fmaf(f1.x, wv.z, s.z);
                s.w = fmaf(f1.y, wv.w, s.w);
            }
        }
    }
    const float k = 0.70710678118654752f;
    float gx = 0.5f * s.x * (1.0f + erff(s.x * k));
    float gy = 0.5f * s.y * (1.0f + erff(s.y * k));
    float gz = 0.5f * s.z * (1.0f + erff(s.z * k));
    float gw = 0.5f * s.w * (1.0f + erff(s.w * k));
    __half2* po = (__half2*)(out + ((size_t)bn * HID) + hc4);
    po[0] = __floats2half2_rn(gx, gy);
    po[1] = __floats2half2_rn(gz, gw);
}

// ---------------- launch ----------------
extern "C" void kernel_launch(void* const* d_in, const int* in_sizes, int n_in,
                              void* d_out, int out_size)
{
    const float* x     = (const float*)d_in[0];
    const float* ln1_g = (const float*)d_in[1];
    const float* ln1_b = (const float*)d_in[2];
    const float* Wk    = (const float*)d_in[3];
    const float* bk    = (const float*)d_in[4];
    const float* Wq    = (const float*)d_in[5];
    const float* bq    = (const float*)d_in[6];
    const float* Wv    = (const float*)d_in[7];
    const float* bv    = (const float*)d_in[8];
    const float* Wr    = (const float*)d_in[9];
    const float* br    = (const float*)d_in[10];
    const float* ln2_g = (const float*)d_in[11];
    const float* ln2_b = (const float*)d_in[12];
    const float* fc1_W = (const float*)d_in[13];
    const float* fc1_b = (const float*)d_in[14];
    const float* dw_W  = (const float*)d_in[15];
    const float* dw_b  = (const float*)d_in[16];
    const float* fc2_W = (const float*)d_in[17];
    const float* fc2_b = (const float*)d_in[18];

    __half *n1h, *keysh, *valsh, *qh, *h1h, *acth, *ctxRh, *Mh, *rWh;
    float  *keysf, *qf, *tx, *ctxp, *wT;
    cudaGetSymbolAddress((void**)&n1h,   g_n1h);
    cudaGetSymbolAddress((void**)&keysf, g_keysf);
    cudaGetSymbolAddress((void**)&keysh, g_keysh);
    cudaGetSymbolAddress((void**)&valsh, g_valsh);
    cudaGetSymbolAddress((void**)&qf,    g_qf);
    cudaGetSymbolAddress((void**)&qh,    g_qh);
    cudaGetSymbolAddress((void**)&tx,    g_tx);
    cudaGetSymbolAddress((void**)&h1h,   g_h1h);
    cudaGetSymbolAddress((void**)&acth,  g_acth);
    cudaGetSymbolAddress((void**)&ctxp,  g_ctxp);
    cudaGetSymbolAddress((void**)&ctxRh, g_ctxRh);
    cudaGetSymbolAddress((void**)&Mh,    g_Mh);
    cudaGetSymbolAddress((void**)&wT,    g_wT);
    cudaGetSymbolAddress((void**)&rWh,   g_rWh);

    cudaFuncSetAttribute(gemm_f16, cudaFuncAttributeMaxDynamicSharedMemorySize, GEMM_SMEM);

    __half* rWk  = rWh;
    __half* rWq  = rWh + 65536;
    __half* rWv  = rWh + 131072;
    __half* rWr  = rWh + 196608;
    __half* rfc1 = rWh + 262144;
    __half* rfc2 = rWh + 524288;

    float* mx  = (float*)d_out;
    float* ctx = mx + MX_SIZE;

    // 0. prep: weights -> fp16, dw transpose
    prep_kernel<<<(786432 + 27648 + 255) / 256, 256>>>(Wk, Wq, Wv, Wr, fc1_W, fc2_W,
                                                       dw_W, rWh, wT);

    // 1. LN1: x -> n1h
    ln_kernel<<<BN_TOK / 8, 256>>>(x, ln1_g, ln1_b, n1h);

    // 2. keys = Wk @ n1^T + bk -> keysf [C, BN] fp32
    gemm_f16<<<dim3(BN_TOK/128, CC/128, 1), 256, GEMM_SMEM>>>(rWk, n1h, keysf, nullptr,
        bk, nullptr, nullptr,
        CC, BN_TOK, CC, CC, CC, BN_TOK, 0, 0, 0, 0, 0, 0, 1);

    // 3. vals = Wv @ n1^T + bv -> valsh [C, BN] fp16
    gemm_f16<<<dim3(BN_TOK/128, CC/128, 1), 256, GEMM_SMEM>>>(rWv, n1h, nullptr, valsh,
        bv, nullptr, nullptr,
        CC, BN_TOK, CC, CC, CC, BN_TOK, 0, 0, 0, 0, 0, 0, 1);

    // 4. q = n1 @ Wq^T + bq -> qf [BN, C] fp32
    gemm_f16<<<dim3(CC/128, BN_TOK/128, 1), 256, GEMM_SMEM>>>(n1h, rWq, qf, nullptr,
        nullptr, bq, nullptr,
        BN_TOK, CC, CC, CC, CC, CC, 0, 0, 0, 0, 0, 0, 1);

    // 5. spatial softmax: keysf -> keysh
    softmax_spatial_kernel<<<2 * CC, 256>>>(keysf, keysh);

    // 6. channel softmax: qf -> qh
    softmax_channel_kernel<<<BN_TOK / 8, 256>>>(qf, qh);

    // 7. context partials (split-K over spatial): keysh x valsh -> ctxp fp32
    gemm_f16<<<dim3(2, 2, BB * SPLITS), 256, GEMM_SMEM>>>(keysh, valsh, ctxp, nullptr,
        nullptr, nullptr, nullptr,
        CC, CC, CHUNK, BN_TOK, BN_TOK, CC,
        (long long)N_TOK, (long long)CHUNK,
        (long long)N_TOK, (long long)CHUNK,
        (long long)SPLITS * CTX_ELE, (long long)CTX_ELE, SPLITS);

    // 8. reduce partials -> ctx (fp32, d_out) + ctxRh (fp16)
    ctx_reduce_kernel<<<512, 256>>>(ctxp, ctx, ctxRh);

    // 9a. M = Wr @ ctx^T per batch -> Mh [c][k] fp16
    gemm_f16<<<dim3(2, 2, BB), 256, GEMM_SMEM>>>(rWr, ctxRh, nullptr, Mh,
        nullptr, nullptr, nullptr,
        CC, CC, CC, CC, CC, CC,
        0, 0, (long long)CTX_ELE, 0, (long long)CTX_ELE, 0, 1);

    // 9b. tx = x + q_sm @ M^T + br  (fused attended + reprojection)
    gemm_f16<<<dim3(CC/128, N_TOK/128, BB), 256, GEMM_SMEM>>>(qh, Mh, tx, nullptr,
        nullptr, br, x,
        N_TOK, CC, CC, CC, CC, CC,
        (long long)N_TOK * CC, 0, (long long)CTX_ELE, 0, (long long)N_TOK * CC, 0, 1);

    // 10. LN2: tx -> n1h
    ln_kernel<<<BN_TOK / 8, 256>>>(tx, ln2_g, ln2_b, n1h);

    // 11. h1 = n2 @ fc1^T + fc1_b -> h1h fp16 (feeds conv)
    gemm_f16<<<dim3(HID/128, BN_TOK/128, 1), 256, GEMM_SMEM>>>(n1h, rfc1, nullptr, h1h,
        nullptr, fc1_b, nullptr,
        BN_TOK, HID, CC, CC, CC, HID, 0, 0, 0, 0, 0, 0, 1);

    // 12. depthwise conv + GELU: h1h -> acth fp16
    dwconv_gelu_kernel<<<(BN_TOK * HID / 4) / 256, 256>>>(h1h, wT, dw_b, acth);

    // 13. mx = tx + act @ fc2^T + fc2_b (fp32, direct to d_out)
    gemm_f16<<<dim3(CC/128, BN_TOK/128, 1), 256, GEMM_SMEM>>>(acth, rfc2, mx, nullptr,
        nullptr, fc2_b, tx,
        BN_TOK, CC, HID, HID, HID, CC, 0, 0, 0, 0, 0, 0, 1);
}

// round 14
// speedup vs baseline: 1.4904x; 1.0257x over previous
#include <cuda_runtime.h>
#include <cuda_fp16.h>
#include <math.h>
#include <stdint.h>

// Problem constants
#define BB      2
#define DD      16
#define HHH     32
#define WWW     32
#define CC      256
#define N_TOK   16384
#define BN_TOK  32768
#define HID     1024
#define SPLITS  16
#define CHUNK   (N_TOK / SPLITS)
#define MX_SIZE ((size_t)BN_TOK * CC)
#define CTX_ELE ((size_t)CC * CC)

// GEMM smem (fp16): BK=32 halfs, row stride 40 halfs = 80B; A/B tiles 128*80 = 10240B
#define AB_BYTES    10240
#define STAGE_BYTES 20480
#define GEMM_SMEM   (3 * STAGE_BYTES)   // 61440 B/CTA; 2 CTAs = 120 KB < 228 KB

// ---------------- scratch ----------------
__device__ __half g_n1h  [(size_t)BN_TOK * CC];
__device__ __half g_kvh  [(size_t)2 * CC * BN_TOK];   // rows 0-255 keys, 256-511 vals
__device__ __half g_qh   [(size_t)BN_TOK * CC];
__device__ float  g_tx   [(size_t)BN_TOK * CC];
__device__ __half g_h1h  [(size_t)BN_TOK * HID];
__device__ __half g_acth [(size_t)BN_TOK * HID];
__device__ float  g_ctxp [(size_t)BB * SPLITS * CC * CC];
__device__ __half g_ctxRh[(size_t)BB * CC * CC];
__device__ __half g_Mh   [(size_t)BB * CC * CC];
__device__ float  g_wT   [27 * HID];
__device__ float  g_bkv  [2 * CC];                    // concat bias [bk; bv]
__device__ __half g_rWh  [4 * 65536 + 2 * 262144];    // fp16 weights (Wk,Wv,Wq,Wr,fc1,fc2)

#define CP16(dst, src) \
    asm volatile("cp.async.ca.shared.global [%0], [%1], 16;" :: "r"(dst), "l"(src))

// ---------------- FP16 tensor-core GEMM: 3-stage cp.async + ldmatrix, m16n8k16 ----------
// C(f32) and/or Ch(f16) = A[M,K]h * B[N,K]h^T (+bias_row +bias_col +resid), f32 accum.
// 128x128 block tile, BK=32 halfs, 256 threads, 8 warps of 64x32.
// K % 32 == 0, K/32 >= 3. __launch_bounds__(256,2) keeps 2 CTAs/SM.
__global__ void __launch_bounds__(256, 2)
gemm_f16(const __half* __restrict__ A, const __half* __restrict__ B,
         float* __restrict__ C, __half* __restrict__ Ch,
         const float* __restrict__ bias_row, const float* __restrict__ bias_col,
         const float* __restrict__ resid,
         int M, int N, int K, int lda, int ldb, int ldc,
         long long sAo, long long sAi, long long sBo, long long sBi,
         long long sCo, long long sCi, int S)
{
    extern __shared__ __half smem_dyn[];
    uint32_t base = (uint32_t)__cvta_generic_to_shared(smem_dyn);

    int z  = blockIdx.z;
    int zo = z / S, zi = z - zo * S;
    const __half* Ab = A + zo * sAo + zi * sAi;
    const __half* Bb = B + zo * sBo + zi * sBi;
    float*  Cb  = C  ? (C  + zo * sCo + zi * sCi) : nullptr;
    __half* Chb = Ch ? (Ch + zo * sCo + zi * sCi) : nullptr;
    const float* Rb = resid ? (resid + zo * sCo + zi * sCi) : nullptr;

    int bm = blockIdx.y << 7, bn = blockIdx.x << 7;
    int tid = threadIdx.x;
    int r   = tid >> 2;          // 0..63
    int c8  = (tid & 3) << 3;    // 0,8,16,24 halfs (16B units)

    const __half* Ag = Ab + (size_t)(bm + r) * lda + c8;
    const __half* Bg = Bb + (size_t)(bn + r) * ldb + c8;
    size_t ldA64 = (size_t)64 * lda, ldB64 = (size_t)64 * ldb;

    uint32_t stA0 = base + (uint32_t)(r * 80 + (c8 << 1));
    uint32_t stA1 = stA0 + (uint32_t)(64 * 80);
    uint32_t stB0 = stA0 + (uint32_t)AB_BYTES;
    uint32_t stB1 = stA1 + (uint32_t)AB_BYTES;

    int lane = tid & 31, warp = tid >> 5;
    int wm = (warp >> 2) << 6;
    int wn = (warp & 3) << 5;
    int gq = lane >> 2, tg = lane & 3;

    uint32_t a_off = base + (uint32_t)((wm + (lane & 15)) * 80 + ((lane >> 4) << 4));
    uint32_t b_off = base + (uint32_t)AB_BYTES
                   + (uint32_t)((wn + ((lane >> 4) << 3) + (lane & 7)) * 80
                                + (((lane >> 3) & 1) << 4));

    float acc[4][4][4];
#pragma unroll
    for (int i = 0; i < 4; i++)
#pragma unroll
        for (int j = 0; j < 4; j++)
#pragma unroll
            for (int l = 0; l < 4; l++) acc[i][j][l] = 0.f;

    int nt = K >> 5;

#define FILL_STAGE(sb)                             \
    do {                                           \
        CP16(stA0 + (sb), Ag);                     \
        CP16(stA1 + (sb), Ag + ldA64);             \
        CP16(stB0 + (sb), Bg);                     \
        CP16(stB1 + (sb), Bg + ldB64);             \
    } while (0)

    FILL_STAGE(0u);
    asm volatile("cp.async.commit_group;");
    Ag += 32; Bg += 32;
    FILL_STAGE((uint32_t)STAGE_BYTES);
    asm volatile("cp.async.commit_group;");
    asm volatile("cp.async.wait_group 1;" ::: "memory");
    __syncthreads();

    int stage = 0, wstage = 2;
    for (int i = 0; i < nt; i++) {
        if (i + 2 < nt) {
            Ag += 32; Bg += 32;
            uint32_t wb = (uint32_t)wstage * STAGE_BYTES;
            FILL_STAGE(wb);
            asm volatile("cp.async.commit_group;");
            wstage = (wstage == 2) ? 0 : wstage + 1;
        }

        uint32_t bufb = (uint32_t)stage * STAGE_BYTES;
#pragma unroll
        for (int kk = 0; kk < 2; kk++) {
            uint32_t kb = (uint32_t)(kk << 5);
            uint32_t a[4][4];
#pragma unroll
            for (int mt = 0; mt < 4; mt++) {
                uint32_t addr = a_off + bufb + kb + (uint32_t)(mt * 1280);
                asm volatile(
                    "ldmatrix.sync.aligned.m8n8.x4.shared.b16 {%0,%1,%2,%3}, [%4];"
                    : "=r"(a[mt][0]), "=r"(a[mt][1]), "=r"(a[mt][2]), "=r"(a[mt][3])
                    : "r"(addr));
            }
            uint32_t b[4][2];
            {
                uint32_t addr0 = b_off + bufb + kb;
                asm volatile(
                    "ldmatrix.sync.aligned.m8n8.x4.shared.b16 {%0,%1,%2,%3}, [%4];"
                    : "=r"(b[0][0]), "=r"(b[0][1]), "=r"(b[1][0]), "=r"(b[1][1])
                    : "r"(addr0));
                uint32_t addr1 = addr0 + 1280u;
                asm volatile(
                    "ldmatrix.sync.aligned.m8n8.x4.shared.b16 {%0,%1,%2,%3}, [%4];"
                    : "=r"(b[2][0]), "=r"(b[2][1]), "=r"(b[3][0]), "=r"(b[3][1])
                    : "r"(addr1));
            }
#pragma unroll
            for (int mt = 0; mt < 4; mt++)
#pragma unroll
                for (int nt2 = 0; nt2 < 4; nt2++) {
                    asm volatile(
                        "mma.sync.aligned.m16n8k16.row.col.f32.f16.f16.f32 "
                        "{%0,%1,%2,%3}, {%4,%5,%6,%7}, {%8,%9}, {%0,%1,%2,%3};\n"
                        : "+f"(acc[mt][nt2][0]), "+f"(acc[mt][nt2][1]),
                          "+f"(acc[mt][nt2][2]), "+f"(acc[mt][nt2][3])
                        : "r"(a[mt][0]), "r"(a[mt][1]), "r"(a[mt][2]), "r"(a[mt][3]),
                          "r"(b[nt2][0]), "r"(b[nt2][1]));
                }
        }

        if (i + 1 < nt) {
            if (i + 2 < nt) { asm volatile("cp.async.wait_group 1;" ::: "memory"); }
            else            { asm volatile("cp.async.wait_group 0;" ::: "memory"); }
            __syncthreads();
        }
        stage = (stage == 2) ? 0 : stage + 1;
    }

    // epilogue
#pragma unroll
    for (int mt = 0; mt < 4; mt++) {
        int row0 = bm + wm + (mt << 4) + gq;
#pragma unroll
        for (int nt2 = 0; nt2 < 4; nt2++) {
            int col = bn + wn + (nt2 << 3) + (tg << 1);
            float bcx = 0.f, bcy = 0.f;
            if (bias_col) { float2 t = *(const float2*)&bias_col[col]; bcx = t.x; bcy = t.y; }
            float br0 = bias_row ? bias_row[row0] : 0.f;
            float br1 = bias_row ? bias_row[row0 + 8] : 0.f;
            size_t o0 = (size_t)row0 * ldc + col;
            size_t o1 = (size_t)(row0 + 8) * ldc + col;
            float2 v0, v1;
            v0.x = acc[mt][nt2][0] + br0 + bcx;
            v0.y = acc[mt][nt2][1] + br0 + bcy;
            v1.x = acc[mt][nt2][2] + br1 + bcx;
            v1.y = acc[mt][nt2][3] + br1 + bcy;
            if (Rb) {
                float2 r0v = *(const float2*)(Rb + o0);
                float2 r1v = *(const float2*)(Rb + o1);
                v0.x += r0v.x; v0.y += r0v.y;
                v1.x += r1v.x; v1.y += r1v.y;
            }
            if (C) {
                *(float2*)(Cb + o0) = v0;
                *(float2*)(Cb + o1) = v1;
            }
            if (Ch) {
                *(__half2*)(Chb + o0) = __floats2half2_rn(v0.x, v0.y);
                *(__half2*)(Chb + o1) = __floats2half2_rn(v1.x, v1.y);
            }
        }
    }
}

// ---------------- fused prep: weights -> fp16 + dw transpose + bias concat -------------
__global__ void prep_kernel(const float* __restrict__ Wk, const float* __restrict__ Wq,
                            const float* __restrict__ Wv, const float* __restrict__ Wr,
                            const float* __restrict__ fc1, const float* __restrict__ fc2,
                            const float* __restrict__ dw,
                            const float* __restrict__ bk, const float* __restrict__ bv,
                            __half* __restrict__ rW, float* __restrict__ wT,
                            float* __restrict__ bkv)
{
    int i = blockIdx.x * 256 + threadIdx.x;
    // layout: [Wk | Wv | Wq | Wr | fc1 | fc2]
    if (i < 65536)        rW[i] = __float2half_rn(Wk[i]);
    else if (i < 131072)  rW[i] = __float2half_rn(Wv[i - 65536]);
    else if (i < 196608)  rW[i] = __float2half_rn(Wq[i - 131072]);
    else if (i < 262144)  rW[i] = __float2half_rn(Wr[i - 196608]);
    else if (i < 524288)  rW[i] = __float2half_rn(fc1[i - 262144]);
    else if (i < 786432)  rW[i] = __float2half_rn(fc2[i - 524288]);
    else if (i < 786432 + 27 * HID) {
        int j = i - 786432;
        int hc = j / 27;
        int t = j - hc * 27;
        wT[t * HID + hc] = dw[j];
    } else {
        int j = i - (786432 + 27 * HID);
        if (j < CC)           bkv[j] = bk[j];
        else if (j < 2 * CC)  bkv[j] = bv[j - CC];
    }
}

// ---------------- LayerNorm over C=256 (fp32 in -> fp16 out) ----------------
__global__ void ln_kernel(const float* __restrict__ x, const float* __restrict__ g,
                          const float* __restrict__ b, __half* __restrict__ out)
{
    int row  = (blockIdx.x << 3) + (threadIdx.x >> 5);
    int lane = threadIdx.x & 31;
    const float4* p = (const float4*)(x + (size_t)row * CC);
    float4 v0 = p[lane], v1 = p[lane + 32];
    float s = v0.x + v0.y + v0.z + v0.w + v1.x + v1.y + v1.z + v1.w;
    float q = v0.x*v0.x + v0.y*v0.y + v0.z*v0.z + v0.w*v0.w
            + v1.x*v1.x + v1.y*v1.y + v1.z*v1.z + v1.w*v1.w;
#pragma unroll
    for (int o = 16; o; o >>= 1) {
        s += __shfl_xor_sync(0xffffffffu, s, o);
        q += __shfl_xor_sync(0xffffffffu, q, o);
    }
    float mean = s * (1.f / 256.f);
    float var  = q * (1.f / 256.f) - mean * mean;
    float rs   = rsqrtf(var + 1e-5f);
    const float4 g0 = ((const float4*)g)[lane], g1 = ((const float4*)g)[lane + 32];
    const float4 b0 = ((const float4*)b)[lane], b1 = ((const float4*)b)[lane + 32];
    __half2* po = (__half2*)(out + (size_t)row * CC);
    po[2*lane]      = __floats2half2_rn((v0.x-mean)*rs*g0.x+b0.x, (v0.y-mean)*rs*g0.y+b0.y);
    po[2*lane+1]    = __floats2half2_rn((v0.z-mean)*rs*g0.z+b0.z, (v0.w-mean)*rs*g0.w+b0.w);
    po[2*lane+64]   = __floats2half2_rn((v1.x-mean)*rs*g1.x+b1.x, (v1.y-mean)*rs*g1.y+b1.y);
    po[2*lane+65]   = __floats2half2_rn((v1.z-mean)*rs*g1.z+b1.z, (v1.w-mean)*rs*g1.w+b1.w);
}

// ------------- spatial softmax, fp16 in-place (row = 16384 contiguous halfs) -------------
__global__ void softmax_spatial_kernel(__half* __restrict__ keys)
{
    __shared__ float red[256];
    __half2* row = (__half2*)(keys + (size_t)blockIdx.x * N_TOK);
    int t = threadIdx.x;
    const int NH2 = N_TOK / 2;

    float m = -1e30f;
    for (int i = t; i < NH2; i += 256) {
        float2 v = __half22float2(row[i]);
        m = fmaxf(m, fmaxf(v.x, v.y));
    }
    red[t] = m; __syncthreads();
    for (int s = 128; s > 0; s >>= 1) { if (t < s) red[t] = fmaxf(red[t], red[t + s]); __syncthreads(); }
    m = red[0]; __syncthreads();

    float sum = 0.f;
    for (int i = t; i < NH2; i += 256) {
        float2 v = __half22float2(row[i]);
        sum += __expf(v.x - m) + __expf(v.y - m);
    }
    red[t] = sum; __syncthreads();
    for (int s = 128; s > 0; s >>= 1) { if (t < s) red[t] += red[t + s]; __syncthreads(); }
    float inv = 1.f / red[0];
    for (int i = t; i < NH2; i += 256) {
        float2 v = __half22float2(row[i]);
        row[i] = __floats2half2_rn(__expf(v.x - m) * inv, __expf(v.y - m) * inv);
    }
}

// ------------- channel softmax, fp16 in-place (warp per row of 256) -------------
__global__ void softmax_channel_kernel(__half* __restrict__ q)
{
    int row  = (blockIdx.x << 3) + (threadIdx.x >> 5);
    int lane = threadIdx.x & 31;
    __half2* p = (__half2*)(q + (size_t)row * CC);
    float2 v[4];
#pragma unroll
    for (int j = 0; j < 4; j++) v[j] = __half22float2(p[lane + 32 * j]);
    float m = -1e30f;
#pragma unroll
    for (int j = 0; j < 4; j++) m = fmaxf(m, fmaxf(v[j].x, v[j].y));
#pragma unroll
    for (int o = 16; o; o >>= 1) m = fmaxf(m, __shfl_xor_sync(0xffffffffu, m, o));
    float s = 0.f;
#pragma unroll
    for (int j = 0; j < 4; j++) {
        v[j].x = __expf(v[j].x - m); v[j].y = __expf(v[j].y - m);
        s += v[j].x + v[j].y;
    }
#pragma unroll
    for (int o = 16; o; o >>= 1) s += __shfl_xor_sync(0xffffffffu, s, o);
    float inv = 1.f / s;
#pragma unroll
    for (int j = 0; j < 4; j++)
        p[lane + 32 * j] = __floats2half2_rn(v[j].x * inv, v[j].y * inv);
}

// -------- split-K reduce -> ctx (d_out, fp32) + ctx fp16 (for M GEMM) ----------
__global__ void ctx_reduce_kernel(const float* __restrict__ part, float* __restrict__ ctx,
                                  __half* __restrict__ ctxRh)
{
    int i = blockIdx.x * 256 + threadIdx.x;
    int b = i >> 16;
    int r = i & 65535;
    float s = 0.f;
#pragma unroll
    for (int sp = 0; sp < SPLITS; sp++)
        s += part[((size_t)(b * SPLITS + sp)) * CTX_ELE + r];
    ctx[i] = s;
    ctxRh[i] = __float2half_rn(s);
}

// ------- depthwise 3x3x3 conv + exact GELU (fp16 in, fp32 accum, fp16 out) -------
__global__ void __launch_bounds__(256)
dwconv_gelu_kernel(const __half* __restrict__ h1h, const float* __restrict__ wT,
                   const float* __restrict__ wb, __half* __restrict__ out)
{
    int t = blockIdx.x * 256 + threadIdx.x;
    int hc4 = (t & 255) << 2;
    int bn  = t >> 8;
    int n = bn & (N_TOK - 1);
    int b = bn >> 14;
    int d = n >> 10;
    int h = (n >> 5) & 31;
    int w = n & 31;

    float4 s = *(const float4*)&wb[hc4];
    const __half* base = h1h + ((size_t)b * N_TOK) * HID + hc4;

#pragma unroll
    for (int kd = -1; kd <= 1; kd++) {
        int zd = d + kd; if ((unsigned)zd >= DD) continue;
#pragma unroll
        for (int kh = -1; kh <= 1; kh++) {
            int zh = h + kh; if ((unsigned)zh >= HHH) continue;
#pragma unroll
            for (int kw = -1; kw <= 1; kw++) {
                int zw = w + kw; if ((unsigned)zw >= WWW) continue;
                int nn = (zd * HHH + zh) * WWW + zw;
                int tap = (kd + 1) * 9 + (kh + 1) * 3 + (kw + 1);
                const __half2* pp = (const __half2*)(base + (size_t)nn * HID);
                float2 f0 = __half22float2(pp[0]);
                float2 f1 = __half22float2(pp[1]);
                float4 wv = *(const float4*)&wT[tap * HID + hc4];
                s.x = fmaf(f0.x, wv.x, s.x);
                s.y = fmaf(f0.y, wv.y, s.y);
                s.z = fmaf(f1.x, wv.z, s.z);
                s.w = fmaf(f1.y, wv.w, s.w);
            }
        }
    }
    const float k = 0.70710678118654752f;
    float gx = 0.5f * s.x * (1.0f + erff(s.x * k));
    float gy = 0.5f * s.y * (1.0f + erff(s.y * k));
    float gz = 0.5f * s.z * (1.0f + erff(s.z * k));
    float gw = 0.5f * s.w * (1.0f + erff(s.w * k));
    __half2* po = (__half2*)(out + ((size_t)bn * HID) + hc4);
    po[0] = __floats2half2_rn(gx, gy);
    po[1] = __floats2half2_rn(gz, gw);
}

// ---------------- launch ----------------
extern "C" void kernel_launch(void* const* d_in, const int* in_sizes, int n_in,
                              void* d_out, int out_size)
{
    const float* x     = (const float*)d_in[0];
    const float* ln1_g = (const float*)d_in[1];
    const float* ln1_b = (const float*)d_in[2];
    const float* Wk    = (const float*)d_in[3];
    const float* bk    = (const float*)d_in[4];
    const float* Wq    = (const float*)d_in[5];
    const float* bq    = (const float*)d_in[6];
    const float* Wv    = (const float*)d_in[7];
    const float* bv    = (const float*)d_in[8];
    const float* Wr    = (const float*)d_in[9];
    const float* br    = (const float*)d_in[10];
    const float* ln2_g = (const float*)d_in[11];
    const float* ln2_b = (const float*)d_in[12];
    const float* fc1_W = (const float*)d_in[13];
    const float* fc1_b = (const float*)d_in[14];
    const float* dw_W  = (const float*)d_in[15];
    const float* dw_b  = (const float*)d_in[16];
    const float* fc2_W = (const float*)d_in[17];
    const float* fc2_b = (const float*)d_in[18];

    __half *n1h, *kvh, *qh, *h1h, *acth, *ctxRh, *Mh, *rWh;
    float  *tx, *ctxp, *wT, *bkv;
    cudaGetSymbolAddress((void**)&n1h,   g_n1h);
    cudaGetSymbolAddress((void**)&kvh,   g_kvh);
    cudaGetSymbolAddress((void**)&qh,    g_qh);
    cudaGetSymbolAddress((void**)&tx,    g_tx);
    cudaGetSymbolAddress((void**)&h1h,   g_h1h);
    cudaGetSymbolAddress((void**)&acth,  g_acth);
    cudaGetSymbolAddress((void**)&ctxp,  g_ctxp);
    cudaGetSymbolAddress((void**)&ctxRh, g_ctxRh);
    cudaGetSymbolAddress((void**)&Mh,    g_Mh);
    cudaGetSymbolAddress((void**)&wT,    g_wT);
    cudaGetSymbolAddress((void**)&bkv,   g_bkv);
    cudaGetSymbolAddress((void**)&rWh,   g_rWh);

    cudaFuncSetAttribute(gemm_f16, cudaFuncAttributeMaxDynamicSharedMemorySize, GEMM_SMEM);

    __half* rWkv = rWh;                    // [Wk;Wv] stacked, 512 x 256
    __half* rWq  = rWh + 131072;
    __half* rWr  = rWh + 196608;
    __half* rfc1 = rWh + 262144;
    __half* rfc2 = rWh + 524288;

    __half* keysh = kvh;                              // [C, BN]
    __half* valsh = kvh + (size_t)CC * BN_TOK;        // [C, BN]

    float* mx  = (float*)d_out;
    float* ctx = mx + MX_SIZE;

    // 0. prep
    prep_kernel<<<(786432 + 27 * HID + 2 * CC + 255) / 256, 256>>>(
        Wk, Wq, Wv, Wr, fc1_W, fc2_W, dw_W, bk, bv, rWh, wT, bkv);

    // 1. LN1: x -> n1h
    ln_kernel<<<BN_TOK / 8, 256>>>(x, ln1_g, ln1_b, n1h);

    // 2. [keys; vals] = [Wk;Wv] @ n1^T + [bk;bv] -> kvh [512, BN] fp16 (single GEMM)
    gemm_f16<<<dim3(BN_TOK/128, 4, 1), 256, GEMM_SMEM>>>(rWkv, n1h, nullptr, kvh,
        bkv, nullptr, nullptr,
        2 * CC, BN_TOK, CC, CC, CC, BN_TOK, 0, 0, 0, 0, 0, 0, 1);

    // 3. q = n1 @ Wq^T + bq -> qh [BN, C] fp16
    gemm_f16<<<dim3(CC/128, BN_TOK/128, 1), 256, GEMM_SMEM>>>(n1h, rWq, nullptr, qh,
        nullptr, bq, nullptr,
        BN_TOK, CC, CC, CC, CC, CC, 0, 0, 0, 0, 0, 0, 1);

    // 4. spatial softmax in-place on keys rows (512 rows of 16384 over (k,b))
    softmax_spatial_kernel<<<2 * CC, 256>>>(keysh);

    // 5. channel softmax in-place on qh
    softmax_channel_kernel<<<BN_TOK / 8, 256>>>(qh);

    // 6. context partials (split-K over spatial)
    gemm_f16<<<dim3(2, 2, BB * SPLITS), 256, GEMM_SMEM>>>(keysh, valsh, ctxp, nullptr,
        nullptr, nullptr, nullptr,
        CC, CC, CHUNK, BN_TOK, BN_TOK, CC,
        (long long)N_TOK, (long long)CHUNK,
        (long long)N_TOK, (long long)CHUNK,
        (long long)SPLITS * CTX_ELE, (long long)CTX_ELE, SPLITS);

    // 7. reduce partials -> ctx (fp32, d_out) + ctxRh (fp16)
    ctx_reduce_kernel<<<512, 256>>>(ctxp, ctx, ctxRh);

    // 8a. M = Wr @ ctx^T per batch -> Mh fp16
    gemm_f16<<<dim3(2, 2, BB), 256, GEMM_SMEM>>>(rWr, ctxRh, nullptr, Mh,
        nullptr, nullptr, nullptr,
        CC, CC, CC, CC, CC, CC,
        0, 0, (long long)CTX_ELE, 0, (long long)CTX_ELE, 0, 1);

    // 8b. tx = x + q_sm @ M^T + br
    gemm_f16<<<dim3(CC/128, N_TOK/128, BB), 256, GEMM_SMEM>>>(qh, Mh, tx, nullptr,
        nullptr, br, x,
        N_TOK, CC, CC, CC, CC, CC,
        (long long)N_TOK * CC, 0, (long long)CTX_ELE, 0, (long long)N_TOK * CC, 0, 1);

    // 9. LN2: tx -> n1h
    ln_kernel<<<BN_TOK / 8, 256>>>(tx, ln2_g, ln2_b, n1h);

    // 10. h1 = n2 @ fc1^T + fc1_b -> h1h fp16
    gemm_f16<<<dim3(HID/128, BN_TOK/128, 1), 256, GEMM_SMEM>>>(n1h, rfc1, nullptr, h1h,
        nullptr, fc1_b, nullptr,
        BN_TOK, HID, CC, CC, CC, HID, 0, 0, 0, 0, 0, 0, 1);

    // 11. depthwise conv + GELU
    dwconv_gelu_kernel<<<(BN_TOK * HID / 4) / 256, 256>>>(h1h, wT, dw_b, acth);

    // 12. mx = tx + act @ fc2^T + fc2_b (fp32, direct to d_out)
    gemm_f16<<<dim3(CC/128, BN_TOK/128, 1), 256, GEMM_SMEM>>>(acth, rfc2, mx, nullptr,
        nullptr, fc2_b, tx,
        BN_TOK, CC, HID, HID, HID, CC, 0, 0, 0, 0, 0, 0, 1);
}

// round 15
// speedup vs baseline: 1.8737x; 1.2572x over previous
#include <cuda_runtime.h>
#include <cuda_fp16.h>
#include <math.h>
#include <stdint.h>

// Problem constants
#define BB      2
#define DD      16
#define HHH     32
#define WWW     32
#define CC      256
#define N_TOK   16384
#define BN_TOK  32768
#define HID     1024
#define SPLITS  16
#define CHUNK   (N_TOK / SPLITS)
#define MX_SIZE ((size_t)BN_TOK * CC)
#define CTX_ELE ((size_t)CC * CC)

// GEMM smem (fp16): BK=32 halfs, row stride 40 halfs = 80B; A/B tiles 128*80 = 10240B
#define AB_BYTES    10240
#define STAGE_BYTES 20480
#define GEMM_SMEM   (3 * STAGE_BYTES)   // 61440 B/CTA; 2 CTAs = 120 KB < 228 KB

// ---------------- scratch ----------------
__device__ __half g_n1h  [(size_t)BN_TOK * CC];
__device__ __half g_kvh  [(size_t)2 * CC * BN_TOK];   // rows 0-255 keys, 256-511 vals
__device__ __half g_qh   [(size_t)BN_TOK * CC];
__device__ __half g_txh  [(size_t)BN_TOK * CC];       // fp16 residual stream
__device__ __half g_h1h  [(size_t)BN_TOK * HID];
__device__ __half g_acth [(size_t)BN_TOK * HID];
__device__ float  g_ctxp [(size_t)BB * SPLITS * CC * CC];
__device__ __half g_ctxRh[(size_t)BB * CC * CC];
__device__ __half g_Mh   [(size_t)BB * CC * CC];
__device__ float  g_wT   [27 * HID];
__device__ float  g_bkv  [2 * CC];
__device__ __half g_rWh  [4 * 65536 + 2 * 262144];

#define CP16(dst, src) \
    asm volatile("cp.async.ca.shared.global [%0], [%1], 16;" :: "r"(dst), "l"(src))

// ---------------- FP16 tensor-core GEMM: 3-stage cp.async + ldmatrix, m16n8k16 ----------
// C(f32) and/or Ch(f16) = A[M,K]h * B[N,K]h^T (+bias_row +bias_col +resid(f32) +residh(f16))
// 128x128 block tile, BK=32 halfs, 256 threads, 8 warps of 64x32. f32 accum.
__global__ void __launch_bounds__(256, 2)
gemm_f16(const __half* __restrict__ A, const __half* __restrict__ B,
         float* __restrict__ C, __half* __restrict__ Ch,
         const float* __restrict__ bias_row, const float* __restrict__ bias_col,
         const float* __restrict__ resid, const __half* __restrict__ residh,
         int M, int N, int K, int lda, int ldb, int ldc,
         long long sAo, long long sAi, long long sBo, long long sBi,
         long long sCo, long long sCi, int S)
{
    extern __shared__ __half smem_dyn[];
    uint32_t base = (uint32_t)__cvta_generic_to_shared(smem_dyn);

    int z  = blockIdx.z;
    int zo = z / S, zi = z - zo * S;
    const __half* Ab = A + zo * sAo + zi * sAi;
    const __half* Bb = B + zo * sBo + zi * sBi;
    float*  Cb  = C  ? (C  + zo * sCo + zi * sCi) : nullptr;
    __half* Chb = Ch ? (Ch + zo * sCo + zi * sCi) : nullptr;
    const float*  Rb  = resid  ? (resid  + zo * sCo + zi * sCi) : nullptr;
    const __half* Rhb = residh ? (residh + zo * sCo + zi * sCi) : nullptr;

    int bm = blockIdx.y << 7, bn = blockIdx.x << 7;
    int tid = threadIdx.x;
    int r   = tid >> 2;
    int c8  = (tid & 3) << 3;

    const __half* Ag = Ab + (size_t)(bm + r) * lda + c8;
    const __half* Bg = Bb + (size_t)(bn + r) * ldb + c8;
    size_t ldA64 = (size_t)64 * lda, ldB64 = (size_t)64 * ldb;

    uint32_t stA0 = base + (uint32_t)(r * 80 + (c8 << 1));
    uint32_t stA1 = stA0 + (uint32_t)(64 * 80);
    uint32_t stB0 = stA0 + (uint32_t)AB_BYTES;
    uint32_t stB1 = stA1 + (uint32_t)AB_BYTES;

    int lane = tid & 31, warp = tid >> 5;
    int wm = (warp >> 2) << 6;
    int wn = (warp & 3) << 5;
    int gq = lane >> 2, tg = lane & 3;

    uint32_t a_off = base + (uint32_t)((wm + (lane & 15)) * 80 + ((lane >> 4) << 4));
    uint32_t b_off = base + (uint32_t)AB_BYTES
                   + (uint32_t)((wn + ((lane >> 4) << 3) + (lane & 7)) * 80
                                + (((lane >> 3) & 1) << 4));

    float acc[4][4][4];
#pragma unroll
    for (int i = 0; i < 4; i++)
#pragma unroll
        for (int j = 0; j < 4; j++)
#pragma unroll
            for (int l = 0; l < 4; l++) acc[i][j][l] = 0.f;

    int nt = K >> 5;

#define FILL_STAGE(sb)                             \
    do {                                           \
        CP16(stA0 + (sb), Ag);                     \
        CP16(stA1 + (sb), Ag + ldA64);             \
        CP16(stB0 + (sb), Bg);                     \
        CP16(stB1 + (sb), Bg + ldB64);             \
    } while (0)

    FILL_STAGE(0u);
    asm volatile("cp.async.commit_group;");
    Ag += 32; Bg += 32;
    FILL_STAGE((uint32_t)STAGE_BYTES);
    asm volatile("cp.async.commit_group;");
    asm volatile("cp.async.wait_group 1;" ::: "memory");
    __syncthreads();

    int stage = 0, wstage = 2;
    for (int i = 0; i < nt; i++) {
        if (i + 2 < nt) {
            Ag += 32; Bg += 32;
            uint32_t wb = (uint32_t)wstage * STAGE_BYTES;
            FILL_STAGE(wb);
            asm volatile("cp.async.commit_group;");
            wstage = (wstage == 2) ? 0 : wstage + 1;
        }

        uint32_t bufb = (uint32_t)stage * STAGE_BYTES;
#pragma unroll
        for (int kk = 0; kk < 2; kk++) {
            uint32_t kb = (uint32_t)(kk << 5);
            uint32_t a[4][4];
#pragma unroll
            for (int mt = 0; mt < 4; mt++) {
                uint32_t addr = a_off + bufb + kb + (uint32_t)(mt * 1280);
                asm volatile(
                    "ldmatrix.sync.aligned.m8n8.x4.shared.b16 {%0,%1,%2,%3}, [%4];"
                    : "=r"(a[mt][0]), "=r"(a[mt][1]), "=r"(a[mt][2]), "=r"(a[mt][3])
                    : "r"(addr));
            }
            uint32_t b[4][2];
            {
                uint32_t addr0 = b_off + bufb + kb;
                asm volatile(
                    "ldmatrix.sync.aligned.m8n8.x4.shared.b16 {%0,%1,%2,%3}, [%4];"
                    : "=r"(b[0][0]), "=r"(b[0][1]), "=r"(b[1][0]), "=r"(b[1][1])
                    : "r"(addr0));
                uint32_t addr1 = addr0 + 1280u;
                asm volatile(
                    "ldmatrix.sync.aligned.m8n8.x4.shared.b16 {%0,%1,%2,%3}, [%4];"
                    : "=r"(b[2][0]), "=r"(b[2][1]), "=r"(b[3][0]), "=r"(b[3][1])
                    : "r"(addr1));
            }
#pragma unroll
            for (int mt = 0; mt < 4; mt++)
#pragma unroll
                for (int nt2 = 0; nt2 < 4; nt2++) {
                    asm volatile(
                        "mma.sync.aligned.m16n8k16.row.col.f32.f16.f16.f32 "
                        "{%0,%1,%2,%3}, {%4,%5,%6,%7}, {%8,%9}, {%0,%1,%2,%3};\n"
                        : "+f"(acc[mt][nt2][0]), "+f"(acc[mt][nt2][1]),
                          "+f"(acc[mt][nt2][2]), "+f"(acc[mt][nt2][3])
                        : "r"(a[mt][0]), "r"(a[mt][1]), "r"(a[mt][2]), "r"(a[mt][3]),
                          "r"(b[nt2][0]), "r"(b[nt2][1]));
                }
        }

        if (i + 1 < nt) {
            if (i + 2 < nt) { asm volatile("cp.async.wait_group 1;" ::: "memory"); }
            else            { asm volatile("cp.async.wait_group 0;" ::: "memory"); }
            __syncthreads();
        }
        stage = (stage == 2) ? 0 : stage + 1;
    }

    // epilogue
#pragma unroll
    for (int mt = 0; mt < 4; mt++) {
        int row0 = bm + wm + (mt << 4) + gq;
#pragma unroll
        for (int nt2 = 0; nt2 < 4; nt2++) {
            int col = bn + wn + (nt2 << 3) + (tg << 1);
            float bcx = 0.f, bcy = 0.f;
            if (bias_col) { float2 t = *(const float2*)&bias_col[col]; bcx = t.x; bcy = t.y; }
            float br0 = bias_row ? bias_row[row0] : 0.f;
            float br1 = bias_row ? bias_row[row0 + 8] : 0.f;
            size_t o0 = (size_t)row0 * ldc + col;
            size_t o1 = (size_t)(row0 + 8) * ldc + col;
            float2 v0, v1;
            v0.x = acc[mt][nt2][0] + br0 + bcx;
            v0.y = acc[mt][nt2][1] + br0 + bcy;
            v1.x = acc[mt][nt2][2] + br1 + bcx;
            v1.y = acc[mt][nt2][3] + br1 + bcy;
            if (Rb) {
                float2 r0v = *(const float2*)(Rb + o0);
                float2 r1v = *(const float2*)(Rb + o1);
                v0.x += r0v.x; v0.y += r0v.y;
                v1.x += r1v.x; v1.y += r1v.y;
            }
            if (Rhb) {
                float2 r0v = __half22float2(*(const __half2*)(Rhb + o0));
                float2 r1v = __half22float2(*(const __half2*)(Rhb + o1));
                v0.x += r0v.x; v0.y += r0v.y;
                v1.x += r1v.x; v1.y += r1v.y;
            }
            if (C) {
                *(float2*)(Cb + o0) = v0;
                *(float2*)(Cb + o1) = v1;
            }
            if (Ch) {
                *(__half2*)(Chb + o0) = __floats2half2_rn(v0.x, v0.y);
                *(__half2*)(Chb + o1) = __floats2half2_rn(v1.x, v1.y);
            }
        }
    }
}

// ---------------- fused prep ----------------
__global__ void prep_kernel(const float* __restrict__ Wk, const float* __restrict__ Wq,
                            const float* __restrict__ Wv, const float* __restrict__ Wr,
                            const float* __restrict__ fc1, const float* __restrict__ fc2,
                            const float* __restrict__ dw,
                            const float* __restrict__ bk, const float* __restrict__ bv,
                            __half* __restrict__ rW, float* __restrict__ wT,
                            float* __restrict__ bkv)
{
    int i = blockIdx.x * 256 + threadIdx.x;
    if (i < 65536)        rW[i] = __float2half_rn(Wk[i]);
    else if (i < 131072)  rW[i] = __float2half_rn(Wv[i - 65536]);
    else if (i < 196608)  rW[i] = __float2half_rn(Wq[i - 131072]);
    else if (i < 262144)  rW[i] = __float2half_rn(Wr[i - 196608]);
    else if (i < 524288)  rW[i] = __float2half_rn(fc1[i - 262144]);
    else if (i < 786432)  rW[i] = __float2half_rn(fc2[i - 524288]);
    else if (i < 786432 + 27 * HID) {
        int j = i - 786432;
        int hc = j / 27;
        int t = j - hc * 27;
        wT[t * HID + hc] = dw[j];
    } else {
        int j = i - (786432 + 27 * HID);
        if (j < CC)           bkv[j] = bk[j];
        else if (j < 2 * CC)  bkv[j] = bv[j - CC];
    }
}

// ---------------- LayerNorm (fp32 in -> fp16 out) ----------------
__global__ void ln_kernel(const float* __restrict__ x, const float* __restrict__ g,
                          const float* __restrict__ b, __half* __restrict__ out)
{
    int row  = (blockIdx.x << 3) + (threadIdx.x >> 5);
    int lane = threadIdx.x & 31;
    const float4* p = (const float4*)(x + (size_t)row * CC);
    float4 v0 = p[lane], v1 = p[lane + 32];
    float s = v0.x + v0.y + v0.z + v0.w + v1.x + v1.y + v1.z + v1.w;
    float q = v0.x*v0.x + v0.y*v0.y + v0.z*v0.z + v0.w*v0.w
            + v1.x*v1.x + v1.y*v1.y + v1.z*v1.z + v1.w*v1.w;
#pragma unroll
    for (int o = 16; o; o >>= 1) {
        s += __shfl_xor_sync(0xffffffffu, s, o);
        q += __shfl_xor_sync(0xffffffffu, q, o);
    }
    float mean = s * (1.f / 256.f);
    float var  = q * (1.f / 256.f) - mean * mean;
    float rs   = rsqrtf(var + 1e-5f);
    const float4 g0 = ((const float4*)g)[lane], g1 = ((const float4*)g)[lane + 32];
    const float4 b0 = ((const float4*)b)[lane], b1 = ((const float4*)b)[lane + 32];
    __half2* po = (__half2*)(out + (size_t)row * CC);
    po[2*lane]      = __floats2half2_rn((v0.x-mean)*rs*g0.x+b0.x, (v0.y-mean)*rs*g0.y+b0.y);
    po[2*lane+1]    = __floats2half2_rn((v0.z-mean)*rs*g0.z+b0.z, (v0.w-mean)*rs*g0.w+b0.w);
    po[2*lane+64]   = __floats2half2_rn((v1.x-mean)*rs*g1.x+b1.x, (v1.y-mean)*rs*g1.y+b1.y);
    po[2*lane+65]   = __floats2half2_rn((v1.z-mean)*rs*g1.z+b1.z, (v1.w-mean)*rs*g1.w+b1.w);
}

// ---------------- LayerNorm (fp16 in -> fp16 out) ----------------
__global__ void ln_kernel_h(const __half* __restrict__ x, const float* __restrict__ g,
                            const float* __restrict__ b, __half* __restrict__ out)
{
    int row  = (blockIdx.x << 3) + (threadIdx.x >> 5);
    int lane = threadIdx.x & 31;
    const __half2* p = (const __half2*)(x + (size_t)row * CC);
    float2 v[4];
#pragma unroll
    for (int j = 0; j < 4; j++) v[j] = __half22float2(p[lane + 32 * j]);
    float s = 0.f, q = 0.f;
#pragma unroll
    for (int j = 0; j < 4; j++) {
        s += v[j].x + v[j].y;
        q += v[j].x * v[j].x + v[j].y * v[j].y;
    }
#pragma unroll
    for (int o = 16; o; o >>= 1) {
        s += __shfl_xor_sync(0xffffffffu, s, o);
        q += __shfl_xor_sync(0xffffffffu, q, o);
    }
    float mean = s * (1.f / 256.f);
    float var  = q * (1.f / 256.f) - mean * mean;
    float rs   = rsqrtf(var + 1e-5f);
    __half2* po = (__half2*)(out + (size_t)row * CC);
#pragma unroll
    for (int j = 0; j < 4; j++) {
        float2 gv = ((const float2*)g)[lane + 32 * j];
        float2 bv = ((const float2*)b)[lane + 32 * j];
        po[lane + 32 * j] = __floats2half2_rn((v[j].x - mean) * rs * gv.x + bv.x,
                                              (v[j].y - mean) * rs * gv.y + bv.y);
    }
}

// ------------- spatial softmax, fp16 in-place -------------
__global__ void softmax_spatial_kernel(__half* __restrict__ keys)
{
    __shared__ float red[256];
    __half2* row = (__half2*)(keys + (size_t)blockIdx.x * N_TOK);
    int t = threadIdx.x;
    const int NH2 = N_TOK / 2;

    float m = -1e30f;
    for (int i = t; i < NH2; i += 256) {
        float2 v = __half22float2(row[i]);
        m = fmaxf(m, fmaxf(v.x, v.y));
    }
    red[t] = m; __syncthreads();
    for (int s = 128; s > 0; s >>= 1) { if (t < s) red[t] = fmaxf(red[t], red[t + s]); __syncthreads(); }
    m = red[0]; __syncthreads();

    float sum = 0.f;
    for (int i = t; i < NH2; i += 256) {
        float2 v = __half22float2(row[i]);
        sum += __expf(v.x - m) + __expf(v.y - m);
    }
    red[t] = sum; __syncthreads();
    for (int s = 128; s > 0; s >>= 1) { if (t < s) red[t] += red[t + s]; __syncthreads(); }
    float inv = 1.f / red[0];
    for (int i = t; i < NH2; i += 256) {
        float2 v = __half22float2(row[i]);
        row[i] = __floats2half2_rn(__expf(v.x - m) * inv, __expf(v.y - m) * inv);
    }
}

// ------------- channel softmax, fp16 in-place -------------
__global__ void softmax_channel_kernel(__half* __restrict__ q)
{
    int row  = (blockIdx.x << 3) + (threadIdx.x >> 5);
    int lane = threadIdx.x & 31;
    __half2* p = (__half2*)(q + (size_t)row * CC);
    float2 v[4];
#pragma unroll
    for (int j = 0; j < 4; j++) v[j] = __half22float2(p[lane + 32 * j]);
    float m = -1e30f;
#pragma unroll
    for (int j = 0; j < 4; j++) m = fmaxf(m, fmaxf(v[j].x, v[j].y));
#pragma unroll
    for (int o = 16; o; o >>= 1) m = fmaxf(m, __shfl_xor_sync(0xffffffffu, m, o));
    float s = 0.f;
#pragma unroll
    for (int j = 0; j < 4; j++) {
        v[j].x = __expf(v[j].x - m); v[j].y = __expf(v[j].y - m);
        s += v[j].x + v[j].y;
    }
#pragma unroll
    for (int o = 16; o; o >>= 1) s += __shfl_xor_sync(0xffffffffu, s, o);
    float inv = 1.f / s;
#pragma unroll
    for (int j = 0; j < 4; j++)
        p[lane + 32 * j] = __floats2half2_rn(v[j].x * inv, v[j].y * inv);
}

// -------- split-K reduce -> ctx (d_out, fp32) + ctx fp16 ----------
__global__ void ctx_reduce_kernel(const float* __restrict__ part, float* __restrict__ ctx,
                                  __half* __restrict__ ctxRh)
{
    int i = blockIdx.x * 256 + threadIdx.x;
    int b = i >> 16;
    int r = i & 65535;
    float s = 0.f;
#pragma unroll
    for (int sp = 0; sp < SPLITS; sp++)
        s += part[((size_t)(b * SPLITS + sp)) * CTX_ELE + r];
    ctx[i] = s;
    ctxRh[i] = __float2half_rn(s);
}

// ------- depthwise conv + GELU: 4 w-positions x 4 channels per thread -------
#define FMA4(A, F0, F1, W)                      \
    do {                                        \
        A.x = fmaf(F0.x, W.x, A.x);             \
        A.y = fmaf(F0.y, W.y, A.y);             \
        A.z = fmaf(F1.x, W.z, A.z);             \
        A.w = fmaf(F1.y, W.w, A.w);             \
    } while (0)

__global__ void __launch_bounds__(256)
dwconv_gelu_kernel(const __half* __restrict__ h1h, const float* __restrict__ wT,
                   const float* __restrict__ wb, __half* __restrict__ out)
{
    int t = blockIdx.x * 256 + threadIdx.x;      // BN_TOK/4 * HID/4 threads
    int hc4 = (t & 255) << 2;                    // channel group
    int q = t >> 8;
    int w0 = (q & 7) << 2;                       // base w (0,4,...,28)
    int rest = q >> 3;
    int h = rest & 31;
    rest >>= 5;
    int d = rest & 15;
    int b = rest >> 4;

    float4 bias = *(const float4*)&wb[hc4];
    float4 a0 = bias, a1 = bias, a2 = bias, a3 = bias;
    const __half* tb = h1h + (size_t)b * N_TOK * HID + hc4;

#pragma unroll
    for (int kd = -1; kd <= 1; kd++) {
        int zd = d + kd; if ((unsigned)zd >= DD) continue;
#pragma unroll
        for (int kh = -1; kh <= 1; kh++) {
            int zh = h + kh; if ((unsigned)zh >= HHH) continue;
            const float* wp = wT + ((kd + 1) * 9 + (kh + 1) * 3) * HID + hc4;
            float4 wv0 = *(const float4*)(wp);
            float4 wv1 = *(const float4*)(wp + HID);
            float4 wv2 = *(const float4*)(wp + 2 * HID);
            const __half* rowp = tb + (size_t)((zd * HHH + zh) * WWW) * HID;

            float2 f0, f1;
            const __half2* pp;
            if (w0 > 0) {
                pp = (const __half2*)(rowp + (size_t)(w0 - 1) * HID);
                f0 = __half22float2(pp[0]); f1 = __half22float2(pp[1]);
                FMA4(a0, f0, f1, wv0);
            }
            pp = (const __half2*)(rowp + (size_t)w0 * HID);
            f0 = __half22float2(pp[0]); f1 = __half22float2(pp[1]);
            FMA4(a1, f0, f1, wv0); FMA4(a0, f0, f1, wv1);

            pp = (const __half2*)(rowp + (size_t)(w0 + 1) * HID);
            f0 = __half22float2(pp[0]); f1 = __half22float2(pp[1]);
            FMA4(a2, f0, f1, wv0); FMA4(a1, f0, f1, wv1); FMA4(a0, f0, f1, wv2);

            pp = (const __half2*)(rowp + (size_t)(w0 + 2) * HID);
            f0 = __half22float2(pp[0]); f1 = __half22float2(pp[1]);
            FMA4(a3, f0, f1, wv0); FMA4(a2, f0, f1, wv1); FMA4(a1, f0, f1, wv2);

            pp = (const __half2*)(rowp + (size_t)(w0 + 3) * HID);
            f0 = __half22float2(pp[0]); f1 = __half22float2(pp[1]);
            FMA4(a3, f0, f1, wv1); FMA4(a2, f0, f1, wv2);

            if (w0 < 28) {
                pp = (const __half2*)(rowp + (size_t)(w0 + 4) * HID);
                f0 = __half22float2(pp[0]); f1 = __half22float2(pp[1]);
                FMA4(a3, f0, f1, wv2);
            }
        }
    }

    const float kgl = 0.70710678118654752f;
    size_t obase = ((size_t)b * N_TOK + (size_t)(d * HHH + h) * WWW + w0) * HID + hc4;
#pragma unroll
    for (int p = 0; p < 4; p++) {
        float4 s = (p == 0) ? a0 : (p == 1) ? a1 : (p == 2) ? a2 : a3;
        float gx = 0.5f * s.x * (1.0f + erff(s.x * kgl));
        float gy = 0.5f * s.y * (1.0f + erff(s.y * kgl));
        float gz = 0.5f * s.z * (1.0f + erff(s.z * kgl));
        float gw = 0.5f * s.w * (1.0f + erff(s.w * kgl));
        __half2* po = (__half2*)(out + obase + (size_t)p * HID);
        po[0] = __floats2half2_rn(gx, gy);
        po[1] = __floats2half2_rn(gz, gw);
    }
}

// ---------------- launch ----------------
extern "C" void kernel_launch(void* const* d_in, const int* in_sizes, int n_in,
                              void* d_out, int out_size)
{
    const float* x     = (const float*)d_in[0];
    const float* ln1_g = (const float*)d_in[1];
    const float* ln1_b = (const float*)d_in[2];
    const float* Wk    = (const float*)d_in[3];
    const float* bk    = (const float*)d_in[4];
    const float* Wq    = (const float*)d_in[5];
    const float* bq    = (const float*)d_in[6];
    const float* Wv    = (const float*)d_in[7];
    const float* bv    = (const float*)d_in[8];
    const float* Wr    = (const float*)d_in[9];
    const float* br    = (const float*)d_in[10];
    const float* ln2_g = (const float*)d_in[11];
    const float* ln2_b = (const float*)d_in[12];
    const float* fc1_W = (const float*)d_in[13];
    const float* fc1_b = (const float*)d_in[14];
    const float* dw_W  = (const float*)d_in[15];
    const float* dw_b  = (const float*)d_in[16];
    const float* fc2_W = (const float*)d_in[17];
    const float* fc2_b = (const float*)d_in[18];

    __half *n1h, *kvh, *qh, *txh, *h1h, *acth, *ctxRh, *Mh, *rWh;
    float  *ctxp, *wT, *bkv;
    cudaGetSymbolAddress((void**)&n1h,   g_n1h);
    cudaGetSymbolAddress((void**)&kvh,   g_kvh);
    cudaGetSymbolAddress((void**)&qh,    g_qh);
    cudaGetSymbolAddress((void**)&txh,   g_txh);
    cudaGetSymbolAddress((void**)&h1h,   g_h1h);
    cudaGetSymbolAddress((void**)&acth,  g_acth);
    cudaGetSymbolAddress((void**)&ctxp,  g_ctxp);
    cudaGetSymbolAddress((void**)&ctxRh, g_ctxRh);
    cudaGetSymbolAddress((void**)&Mh,    g_Mh);
    cudaGetSymbolAddress((void**)&wT,    g_wT);
    cudaGetSymbolAddress((void**)&bkv,   g_bkv);
    cudaGetSymbolAddress((void**)&rWh,   g_rWh);

    cudaFuncSetAttribute(gemm_f16, cudaFuncAttributeMaxDynamicSharedMemorySize, GEMM_SMEM);

    __half* rWkv = rWh;
    __half* rWq  = rWh + 131072;
    __half* rWr  = rWh + 196608;
    __half* rfc1 = rWh + 262144;
    __half* rfc2 = rWh + 524288;

    __half* keysh = kvh;
    __half* valsh = kvh + (size_t)CC * BN_TOK;

    float* mx  = (float*)d_out;
    float* ctx = mx + MX_SIZE;

    // 0. prep
    prep_kernel<<<(786432 + 27 * HID + 2 * CC + 255) / 256, 256>>>(
        Wk, Wq, Wv, Wr, fc1_W, fc2_W, dw_W, bk, bv, rWh, wT, bkv);

    // 1. LN1: x -> n1h
    ln_kernel<<<BN_TOK / 8, 256>>>(x, ln1_g, ln1_b, n1h);

    // 2. [keys; vals] = [Wk;Wv] @ n1^T + [bk;bv] -> kvh [512, BN] fp16
    gemm_f16<<<dim3(BN_TOK/128, 4, 1), 256, GEMM_SMEM>>>(rWkv, n1h, nullptr, kvh,
        bkv, nullptr, nullptr, nullptr,
        2 * CC, BN_TOK, CC, CC, CC, BN_TOK, 0, 0, 0, 0, 0, 0, 1);

    // 3. q = n1 @ Wq^T + bq -> qh [BN, C] fp16
    gemm_f16<<<dim3(CC/128, BN_TOK/128, 1), 256, GEMM_SMEM>>>(n1h, rWq, nullptr, qh,
        nullptr, bq, nullptr, nullptr,
        BN_TOK, CC, CC, CC, CC, CC, 0, 0, 0, 0, 0, 0, 1);

    // 4. spatial softmax in-place on keys
    softmax_spatial_kernel<<<2 * CC, 256>>>(keysh);

    // 5. channel softmax in-place on qh
    softmax_channel_kernel<<<BN_TOK / 8, 256>>>(qh);

    // 6. context partials (split-K over spatial)
    gemm_f16<<<dim3(2, 2, BB * SPLITS), 256, GEMM_SMEM>>>(keysh, valsh, ctxp, nullptr,
        nullptr, nullptr, nullptr, nullptr,
        CC, CC, CHUNK, BN_TOK, BN_TOK, CC,
        (long long)N_TOK, (long long)CHUNK,
        (long long)N_TOK, (long long)CHUNK,
        (long long)SPLITS * CTX_ELE, (long long)CTX_ELE, SPLITS);

    // 7. reduce partials -> ctx (fp32, d_out) + ctxRh (fp16)
    ctx_reduce_kernel<<<512, 256>>>(ctxp, ctx, ctxRh);

    // 8a. M = Wr @ ctx^T per batch -> Mh fp16
    gemm_f16<<<dim3(2, 2, BB), 256, GEMM_SMEM>>>(rWr, ctxRh, nullptr, Mh,
        nullptr, nullptr, nullptr, nullptr,
        CC, CC, CC, CC, CC, CC,
        0, 0, (long long)CTX_ELE, 0, (long long)CTX_ELE, 0, 1);

    // 8b. txh = x + q_sm @ M^T + br  (fp16 residual stream, fp32 x residual)
    gemm_f16<<<dim3(CC/128, N_TOK/128, BB), 256, GEMM_SMEM>>>(qh, Mh, nullptr, txh,
        nullptr, br, x, nullptr,
        N_TOK, CC, CC, CC, CC, CC,
        (long long)N_TOK * CC, 0, (long long)CTX_ELE, 0, (long long)N_TOK * CC, 0, 1);

    // 9. LN2: txh -> n1h (fp16 in)
    ln_kernel_h<<<BN_TOK / 8, 256>>>(txh, ln2_g, ln2_b, n1h);

    // 10. h1 = n2 @ fc1^T + fc1_b -> h1h fp16
    gemm_f16<<<dim3(HID/128, BN_TOK/128, 1), 256, GEMM_SMEM>>>(n1h, rfc1, nullptr, h1h,
        nullptr, fc1_b, nullptr, nullptr,
        BN_TOK, HID, CC, CC, CC, HID, 0, 0, 0, 0, 0, 0, 1);

    // 11. depthwise conv + GELU (4 w-positions per thread)
    dwconv_gelu_kernel<<<(BN_TOK / 4) * (HID / 4) / 256, 256>>>(h1h, wT, dw_b, acth);

    // 12. mx = txh + act @ fc2^T + fc2_b (fp32 out, fp16 residual)
    gemm_f16<<<dim3(CC/128, BN_TOK/128, 1), 256, GEMM_SMEM>>>(acth, rfc2, mx, nullptr,
        nullptr, fc2_b, nullptr, txh,
        BN_TOK, CC, HID, HID, HID, CC, 0, 0, 0, 0, 0, 0, 1);
}